// round 1
// baseline (speedup 1.0000x reference)
#include <cuda_runtime.h>
#include <cstdint>

#define NCELL 500000
#define MNET  450000
#define EKE   2000000
#define ESE   500000
#define EMB   64
#define VN    64
#define NL    3
#define CATD  256   // (NL+1)*EMB
#define OUTD  8

// ---------------- scratch (static device allocations) ----------------
__device__ float g_rsq_n[NCELL];
__device__ float g_rsq_e[MNET];
__device__ float g_ew[EKE];
__device__ float g_cat[(size_t)NCELL * CATD];   // node_list, interleaved per-row [n][l*64+j]
__device__ float g_x[(size_t)NCELL * EMB];
__device__ float g_net[(size_t)MNET * EMB];
__device__ float g_agg[(size_t)MNET * EMB];
__device__ float g_back[(size_t)NCELL * EMB];
__device__ float g_vn[VN * EMB];
__device__ float g_pool[VN * EMB];
__device__ float g_cnt[VN];

// ---------------- utility kernels ----------------
__global__ void k_zero(float* p, int n) {
    int i = blockIdx.x * blockDim.x + threadIdx.x;
    if (i < n) p[i] = 0.f;
}

__global__ void k_zero4(float4* p, int n4) {
    int i = blockIdx.x * blockDim.x + threadIdx.x;
    if (i < n4) p[i] = make_float4(0.f, 0.f, 0.f, 0.f);
}

__global__ void k_degree(const int* __restrict__ sn, const int* __restrict__ se) {
    int i = blockIdx.x * blockDim.x + threadIdx.x;
    if (i < EKE) {
        atomicAdd(&g_rsq_n[sn[i]], 1.f);
        atomicAdd(&g_rsq_e[se[i]], 1.f);
    }
}

__global__ void k_rsq(float* p, int n) {
    int i = blockIdx.x * blockDim.x + threadIdx.x;
    if (i < n) p[i] = rsqrtf(fmaxf(p[i], 1.f));
}

__global__ void k_ew(const int* __restrict__ sn, const int* __restrict__ se) {
    int i = blockIdx.x * blockDim.x + threadIdx.x;
    if (i < EKE) g_ew[i] = g_rsq_n[sn[i]] * g_rsq_e[se[i]];
}

__global__ void k_cnt(const int* __restrict__ batch) {
    __shared__ float s[VN];
    int tid = threadIdx.x;
    if (tid < VN) s[tid] = 0.f;
    __syncthreads();
    for (int n = blockIdx.x * blockDim.x + tid; n < NCELL; n += gridDim.x * blockDim.x)
        atomicAdd(&s[batch[n]], 1.f);
    __syncthreads();
    if (tid < VN) atomicAdd(&g_cnt[tid], s[tid]);
}

__global__ void k_vninit(const float* __restrict__ vn_emb) {
    int i = blockIdx.x * blockDim.x + threadIdx.x;
    if (i < VN * EMB) g_vn[i] = vn_emb[i & 63];
}

// ---------------- embedding: relu(feat[16] @ W[16,64] + b) ----------------
__global__ void k_embed(const float* __restrict__ feat,
                        const float* __restrict__ w, const float* __restrict__ b,
                        float* __restrict__ out, int nrows, int ostride) {
    __shared__ float s_w[16 * EMB];
    __shared__ float s_b[EMB];
    int tid = threadIdx.x;
    for (int i = tid; i < 16 * EMB; i += 256) s_w[i] = w[i];
    if (tid < EMB) s_b[tid] = b[tid];
    __syncthreads();
    int j = tid & 63, r = tid >> 6;
    int base = blockIdx.x * 16;
    for (int g = 0; g < 16; g += 4) {
        int row = base + g + r;
        if (row < nrows) {
            const float* f = feat + (size_t)row * 16;
            float acc = s_b[j];
            #pragma unroll
            for (int k = 0; k < 16; k++) acc += f[k] * s_w[k * EMB + j];
            out[(size_t)row * ostride + j] = fmaxf(acc, 0.f);
        }
    }
}

// ---------------- x = node_list[l] + vn[batch] ----------------
__global__ void k_make_x(const int* __restrict__ batch, int l) {
    int i = blockIdx.x * blockDim.x + threadIdx.x;
    if (i < NCELL * EMB) {
        int n = i >> 6, j = i & 63;
        g_x[i] = g_cat[(size_t)n * CATD + l * EMB + j] + g_vn[batch[n] * EMB + j];
    }
}

// ---------------- VN pooling: g_pool[v] += sum of x over batch==v ----------------
__global__ void k_pool(const int* __restrict__ batch) {
    __shared__ float s[VN * EMB];
    int tid = threadIdx.x;
    for (int i = tid; i < VN * EMB; i += 256) s[i] = 0.f;
    __syncthreads();
    int j = tid & 63, r = tid >> 6;
    for (int n = blockIdx.x * 4 + r; n < NCELL; n += gridDim.x * 4) {
        int b = batch[n];
        atomicAdd(&s[b * EMB + j], g_x[(size_t)n * EMB + j]);
    }
    __syncthreads();
    for (int i = tid; i < VN * EMB; i += 256) atomicAdd(&g_pool[i], s[i]);
}

// ---------------- edge scatter-add: dst[di[e]] += src[si[e]] * (wt ? wt[e] : 1) ----------------
__global__ void k_edge(const int* __restrict__ si, const int* __restrict__ di,
                       const float* __restrict__ wt,
                       const float* __restrict__ srcbuf, float* __restrict__ dstbuf, int E) {
    int t = blockIdx.x * blockDim.x + threadIdx.x;
    if (t >= E * 16) return;
    int e = t >> 4, c = t & 15;
    int sn = si[e], dn = di[e];
    float4 v = reinterpret_cast<const float4*>(srcbuf)[(size_t)sn * 16 + c];
    if (wt) {
        float w = wt[e];
        v.x *= w; v.y *= w; v.z *= w; v.w *= w;
    }
    float* dst = dstbuf + (size_t)dn * EMB + c * 4;
    asm volatile("red.global.add.v4.f32 [%0], {%1,%2,%3,%4};"
                 :: "l"(dst), "f"(v.x), "f"(v.y), "f"(v.z), "f"(v.w) : "memory");
}

// ---------------- conv: out = relu((inA + inB) @ W[64,64] + b) ----------------
__global__ void k_conv(const float* __restrict__ inA, const float* __restrict__ inB,
                       const float* __restrict__ w, const float* __restrict__ b,
                       float* __restrict__ out, int nrows, int ostride, int ooff) {
    __shared__ float s_w[EMB * EMB];
    __shared__ float s_b[EMB];
    __shared__ float s_in[4][EMB];
    int tid = threadIdx.x;
    for (int i = tid; i < EMB * EMB; i += 256) s_w[i] = w[i];
    if (tid < EMB) s_b[tid] = b[tid];
    int j = tid & 63, r = tid >> 6;
    size_t base = (size_t)blockIdx.x * 16;
    for (int g = 0; g < 16; g += 4) {
        size_t row = base + g + r;
        __syncthreads();
        if (row < (size_t)nrows)
            s_in[r][j] = inA[row * EMB + j] + inB[row * EMB + j];
        __syncthreads();
        if (row < (size_t)nrows) {
            float acc = s_b[j];
            #pragma unroll
            for (int k = 0; k < EMB; k++) acc += s_in[r][k] * s_w[k * EMB + j];
            out[row * ostride + ooff + j] = fmaxf(acc, 0.f);
        }
    }
}

// ---------------- VN update: vn += relu((pool/cnt + vn) @ W + b) ----------------
__global__ void k_vn(const float* __restrict__ w, const float* __restrict__ b) {
    int v = blockIdx.x, j = threadIdx.x;
    __shared__ float t[EMB];
    float c = fmaxf(g_cnt[v], 1.f);
    t[j] = g_pool[v * EMB + j] / c + g_vn[v * EMB + j];
    __syncthreads();
    float acc = b[j];
    #pragma unroll
    for (int k = 0; k < EMB; k++) acc += t[k] * w[k * EMB + j];
    g_vn[v * EMB + j] += fmaxf(acc, 0.f);
}

// ---------------- head: nodes = relu(relu(cat@fc1)@fc2), ret = cat@outw ----------------
__global__ __launch_bounds__(256) void k_head(
    const float* __restrict__ fc1w, const float* __restrict__ fc1b,
    const float* __restrict__ fc2w, const float* __restrict__ fc2b,
    const float* __restrict__ outw, const float* __restrict__ outb,
    const float* __restrict__ cat,
    float* __restrict__ nodes_out, float* __restrict__ ret_out) {
    __shared__ float As[32][64];
    __shared__ float Hs[32][257];   // pad to kill fc2 bank conflicts
    __shared__ float rpart[32][8];
    int tid = threadIdx.x;          // = output column j of fc1
    int j = tid;
    size_t n0 = (size_t)blockIdx.x * 32;
    float acc[32];
    float bj = fc1b[j];
    #pragma unroll
    for (int i = 0; i < 32; i++) acc[i] = bj;

    for (int kc = 0; kc < 4; kc++) {
        __syncthreads();
        #pragma unroll
        for (int q = 0; q < 8; q++) {
            int idx = tid + q * 256;       // 0..2047
            int i = idx >> 6, k = idx & 63;
            size_t row = n0 + i;
            As[i][k] = (row < NCELL) ? cat[row * CATD + kc * 64 + k] : 0.f;
        }
        __syncthreads();
        #pragma unroll
        for (int k = 0; k < 64; k++) {
            float bkj = fc1w[(kc * 64 + k) * 256 + j];
            #pragma unroll
            for (int i = 0; i < 32; i++) acc[i] += As[i][k] * bkj;
        }
    }
    #pragma unroll
    for (int i = 0; i < 32; i++) Hs[i][j] = fmaxf(acc[i], 0.f);
    __syncthreads();

    int i2 = tid >> 3, o = tid & 7;
    size_t row = n0 + i2;
    {
        float a = fc2b[o];
        #pragma unroll 8
        for (int jj = 0; jj < 256; jj++) a += Hs[i2][jj] * fc2w[jj * 8 + o];
        if (row < NCELL) nodes_out[row * OUTD + o] = fmaxf(a, 0.f);
    }
    {
        float a = 0.f;
        if (row < NCELL) {
            const float* crow = cat + row * CATD;
            #pragma unroll
            for (int jj = o * 32; jj < o * 32 + 32; jj++) a += crow[jj] * outw[jj];
        }
        rpart[i2][o] = a;
        __syncthreads();
        if (o == 0 && row < NCELL) {
            float s = outb[0];
            #pragma unroll
            for (int q = 0; q < 8; q++) s += rpart[i2][q];
            ret_out[row] = s;
        }
    }
}

// ---------------- launch ----------------
static inline int cdiv(long long a, long long b) { return (int)((a + b - 1) / b); }

extern "C" void kernel_launch(void* const* d_in, const int* in_sizes, int n_in,
                              void* d_out, int out_size) {
    const float* node_f     = (const float*)d_in[0];
    const float* net_f      = (const float*)d_in[1];
    const int*   sink_node  = (const int*)d_in[2];
    const int*   sink_net   = (const int*)d_in[3];
    const int*   src_node   = (const int*)d_in[4];
    const int*   src_net    = (const int*)d_in[5];
    const int*   batch      = (const int*)d_in[6];
    // d_in[7] = num_vn (scalar, compile-time VN=64)
    const float* w_node     = (const float*)d_in[8];
    const float* b_node     = (const float*)d_in[9];
    const float* w_net      = (const float*)d_in[10];
    const float* b_net      = (const float*)d_in[11];
    const float* vn_emb     = (const float*)d_in[12];
    const float* vn_mlp_w   = (const float*)d_in[13];
    const float* vn_mlp_b   = (const float*)d_in[14];
    const float* conv_net_w = (const float*)d_in[15];
    const float* conv_net_b = (const float*)d_in[16];
    const float* conv_node_w= (const float*)d_in[17];
    const float* conv_node_b= (const float*)d_in[18];
    const float* fc1_w      = (const float*)d_in[19];
    const float* fc1_b      = (const float*)d_in[20];
    const float* fc2_w      = (const float*)d_in[21];
    const float* fc2_b      = (const float*)d_in[22];
    const float* out_w      = (const float*)d_in[23];
    const float* out_b      = (const float*)d_in[24];

    float *p_rsqn, *p_rsqe, *p_ew, *p_cat, *p_x, *p_net, *p_agg, *p_back, *p_pool, *p_cnt;
    cudaGetSymbolAddress((void**)&p_rsqn, g_rsq_n);
    cudaGetSymbolAddress((void**)&p_rsqe, g_rsq_e);
    cudaGetSymbolAddress((void**)&p_ew,   g_ew);
    cudaGetSymbolAddress((void**)&p_cat,  g_cat);
    cudaGetSymbolAddress((void**)&p_x,    g_x);
    cudaGetSymbolAddress((void**)&p_net,  g_net);
    cudaGetSymbolAddress((void**)&p_agg,  g_agg);
    cudaGetSymbolAddress((void**)&p_back, g_back);
    cudaGetSymbolAddress((void**)&p_pool, g_pool);
    cudaGetSymbolAddress((void**)&p_cnt,  g_cnt);

    // --- degrees / edge weights / counts ---
    k_zero<<<cdiv(NCELL, 256), 256>>>(p_rsqn, NCELL);
    k_zero<<<cdiv(MNET, 256), 256>>>(p_rsqe, MNET);
    k_zero<<<1, 64>>>(p_cnt, VN);
    k_degree<<<cdiv(EKE, 256), 256>>>(sink_node, sink_net);
    k_rsq<<<cdiv(NCELL, 256), 256>>>(p_rsqn, NCELL);
    k_rsq<<<cdiv(MNET, 256), 256>>>(p_rsqe, MNET);
    k_ew<<<cdiv(EKE, 256), 256>>>(sink_node, sink_net);
    k_cnt<<<128, 256>>>(batch);

    // --- input embeddings ---
    k_embed<<<cdiv(NCELL, 16), 256>>>(node_f, w_node, b_node, p_cat, NCELL, CATD);
    k_embed<<<cdiv(MNET, 16), 256>>>(net_f, w_net, b_net, p_net, MNET, EMB);
    k_vninit<<<cdiv(VN * EMB, 256), 256>>>(vn_emb);

    // --- layers ---
    for (int l = 0; l < NL; l++) {
        k_make_x<<<cdiv((long long)NCELL * EMB, 256), 256>>>(batch, l);
        if (l < NL - 1) {
            k_zero<<<cdiv(VN * EMB, 256), 256>>>(p_pool, VN * EMB);
            k_pool<<<128, 256>>>(batch);
        }
        k_zero4<<<cdiv((long long)MNET * 16, 256), 256>>>((float4*)p_agg, MNET * 16);
        k_edge<<<cdiv((long long)ESE * 16, 256), 256>>>(src_node, src_net, nullptr, p_x, p_agg, ESE);
        k_edge<<<cdiv((long long)EKE * 16, 256), 256>>>(sink_node, sink_net, p_ew, p_x, p_agg, EKE);
        k_conv<<<cdiv(MNET, 16), 256>>>(p_net, p_agg, conv_net_w + l * 4096, conv_net_b + l * 64,
                                        p_net, MNET, EMB, 0);
        k_zero4<<<cdiv((long long)NCELL * 16, 256), 256>>>((float4*)p_back, NCELL * 16);
        k_edge<<<cdiv((long long)EKE * 16, 256), 256>>>(sink_net, sink_node, p_ew, p_net, p_back, EKE);
        k_conv<<<cdiv(NCELL, 16), 256>>>(p_x, p_back, conv_node_w + l * 4096, conv_node_b + l * 64,
                                         p_cat, NCELL, CATD, (l + 1) * 64);
        if (l < NL - 1)
            k_vn<<<VN, EMB>>>(vn_mlp_w + l * 4096, vn_mlp_b + l * 64);
    }

    // --- head ---
    float* nodes_out = (float*)d_out;
    float* ret_out = (float*)d_out + (size_t)NCELL * OUTD;
    k_head<<<cdiv(NCELL, 32), 256>>>(fc1_w, fc1_b, fc2_w, fc2_b, out_w, out_b,
                                     p_cat, nodes_out, ret_out);
}

// round 2
// speedup vs baseline: 1.1048x; 1.1048x over previous
#include <cuda_runtime.h>
#include <cstdint>

#define NCELL 500000
#define MNET  450000
#define EKE   2000000
#define ESE   500000
#define ECOMB (EKE + ESE)
#define EMB   64
#define VN    64
#define NL    3
#define CATD  256
#define OUTD  8

// ---------------- scratch ----------------
__device__ int   g_cnt_n[NCELL];          // sink edges per node
__device__ int   g_cnt_e[MNET];           // sink edges per net
__device__ int   g_cnt_comb[MNET];        // sink+src edges per net
__device__ float g_rsq_n[NCELL];
__device__ float g_rsq_e[MNET];
__device__ float g_ew[EKE];
__device__ int   g_off_net[MNET + 1];
__device__ int   g_cur_net[MNET];
__device__ int   g_off_node[NCELL + 1];
__device__ int   g_cur_node[NCELL];
__device__ int2  g_csr_net[ECOMB];        // (src_node, weight bits)
__device__ int2  g_csr_node[EKE];         // (net, weight bits)
__device__ int   g_partial[1024];
__device__ float g_cat[(size_t)NCELL * CATD];
__device__ float g_x[(size_t)NCELL * EMB];
__device__ float g_net[(size_t)MNET * EMB];
__device__ float g_vn[VN * EMB];
__device__ float g_pool[VN * EMB];
__device__ float g_cntvn[VN];

// ---------------- utility ----------------
__global__ void k_zeroi(int* p, int n) {
    int i = blockIdx.x * blockDim.x + threadIdx.x;
    if (i < n) p[i] = 0;
}
__global__ void k_zerof(float* p, int n) {
    int i = blockIdx.x * blockDim.x + threadIdx.x;
    if (i < n) p[i] = 0.f;
}
__global__ void k_count_sink(const int* __restrict__ sn, const int* __restrict__ se) {
    int i = blockIdx.x * blockDim.x + threadIdx.x;
    if (i < EKE) { atomicAdd(&g_cnt_n[sn[i]], 1); atomicAdd(&g_cnt_e[se[i]], 1); }
}
__global__ void k_count_src(const int* __restrict__ se) {
    int i = blockIdx.x * blockDim.x + threadIdx.x;
    if (i < ESE) atomicAdd(&g_cnt_comb[se[i]], 1);
}
__global__ void k_addcnt() {
    int i = blockIdx.x * blockDim.x + threadIdx.x;
    if (i < MNET) g_cnt_comb[i] += g_cnt_e[i];
}
__global__ void k_rsq_n() {
    int i = blockIdx.x * blockDim.x + threadIdx.x;
    if (i < NCELL) g_rsq_n[i] = rsqrtf(fmaxf((float)g_cnt_n[i], 1.f));
}
__global__ void k_rsq_e() {
    int i = blockIdx.x * blockDim.x + threadIdx.x;
    if (i < MNET) g_rsq_e[i] = rsqrtf(fmaxf((float)g_cnt_e[i], 1.f));
}
__global__ void k_ew(const int* __restrict__ sn, const int* __restrict__ se) {
    int i = blockIdx.x * blockDim.x + threadIdx.x;
    if (i < EKE) g_ew[i] = g_rsq_n[sn[i]] * g_rsq_e[se[i]];
}
__global__ void k_sentinel(int* a, int idx, int val) { a[idx] = val; }

// ---------------- 3-phase exclusive scan (n <= 1024*1024) ----------------
__global__ void k_scan1(const int* __restrict__ cnt, int n) {
    __shared__ int s[256];
    int base = blockIdx.x * 1024, t = threadIdx.x;
    int sum = 0;
    #pragma unroll
    for (int q = 0; q < 4; q++) { int i = base + q * 256 + t; sum += (i < n) ? cnt[i] : 0; }
    s[t] = sum; __syncthreads();
    for (int st = 128; st > 0; st >>= 1) {
        if (t < st) s[t] += s[t + st];
        __syncthreads();
    }
    if (t == 0) g_partial[blockIdx.x] = s[0];
}
__global__ void k_scan2(int nb) {
    __shared__ int s[1024];
    int t = threadIdx.x;
    int v = (t < nb) ? g_partial[t] : 0;
    s[t] = v; __syncthreads();
    for (int st = 1; st < 1024; st <<= 1) {
        int a = (t >= st) ? s[t - st] : 0;
        __syncthreads();
        s[t] += a; __syncthreads();
    }
    if (t < nb) g_partial[t] = s[t] - v;
}
__global__ void k_scan3(const int* __restrict__ cnt, int n, int* __restrict__ off, int* __restrict__ cur) {
    __shared__ int s[256];
    int t = threadIdx.x, base = blockIdx.x * 1024;
    int v[4], sum = 0;
    #pragma unroll
    for (int q = 0; q < 4; q++) { int i = base + t * 4 + q; v[q] = (i < n) ? cnt[i] : 0; sum += v[q]; }
    s[t] = sum; __syncthreads();
    int mine = sum;
    for (int st = 1; st < 256; st <<= 1) {
        int a = (t >= st) ? s[t - st] : 0;
        __syncthreads();
        s[t] += a; __syncthreads();
    }
    int ex = s[t] - mine + g_partial[blockIdx.x];
    #pragma unroll
    for (int q = 0; q < 4; q++) {
        int i = base + t * 4 + q;
        if (i < n) { off[i] = ex; cur[i] = ex; ex += v[q]; }
    }
}

// ---------------- CSR scatters ----------------
__global__ void k_scat_net_src(const int* __restrict__ sn, const int* __restrict__ se) {
    int e = blockIdx.x * blockDim.x + threadIdx.x;
    if (e < ESE) {
        int pos = atomicAdd(&g_cur_net[se[e]], 1);
        g_csr_net[pos] = make_int2(sn[e], __float_as_int(1.f));
    }
}
__global__ void k_scat_net_sink(const int* __restrict__ sn, const int* __restrict__ se) {
    int e = blockIdx.x * blockDim.x + threadIdx.x;
    if (e < EKE) {
        int pos = atomicAdd(&g_cur_net[se[e]], 1);
        g_csr_net[pos] = make_int2(sn[e], __float_as_int(g_ew[e]));
    }
}
__global__ void k_scat_node(const int* __restrict__ sn, const int* __restrict__ se) {
    int e = blockIdx.x * blockDim.x + threadIdx.x;
    if (e < EKE) {
        int pos = atomicAdd(&g_cur_node[sn[e]], 1);
        g_csr_node[pos] = make_int2(se[e], __float_as_int(g_ew[e]));
    }
}

// ---------------- per-VN node counts ----------------
__global__ void k_cnt(const int* __restrict__ batch) {
    __shared__ float s[VN];
    int tid = threadIdx.x;
    if (tid < VN) s[tid] = 0.f;
    __syncthreads();
    for (int n = blockIdx.x * blockDim.x + tid; n < NCELL; n += gridDim.x * blockDim.x)
        atomicAdd(&s[batch[n]], 1.f);
    __syncthreads();
    if (tid < VN) atomicAdd(&g_cntvn[tid], s[tid]);
}
__global__ void k_vninit(const float* __restrict__ vn_emb) {
    int i = blockIdx.x * blockDim.x + threadIdx.x;
    if (i < VN * EMB) g_vn[i] = vn_emb[i & 63];
}

// ---------------- embedding: relu(feat[16] @ W[16,64] + b) ----------------
__global__ void k_embed(const float* __restrict__ feat,
                        const float* __restrict__ w, const float* __restrict__ b,
                        float* __restrict__ out, int nrows, int ostride) {
    __shared__ float s_w[16 * EMB];
    __shared__ float s_b[EMB];
    int tid = threadIdx.x;
    for (int i = tid; i < 16 * EMB; i += 256) s_w[i] = w[i];
    if (tid < EMB) s_b[tid] = b[tid];
    __syncthreads();
    int j = tid & 63, r = tid >> 6;
    int base = blockIdx.x * 16;
    for (int g = 0; g < 16; g += 4) {
        int row = base + g + r;
        if (row < nrows) {
            const float* f = feat + (size_t)row * 16;
            float acc = s_b[j];
            #pragma unroll
            for (int k = 0; k < 16; k++) acc += f[k] * s_w[k * EMB + j];
            out[(size_t)row * ostride + j] = fmaxf(acc, 0.f);
        }
    }
}

// ---------------- x = node_list[l] + vn[batch] ----------------
__global__ void k_make_x(const int* __restrict__ batch, int l) {
    int i = blockIdx.x * blockDim.x + threadIdx.x;
    if (i < NCELL * EMB) {
        int n = i >> 6, j = i & 63;
        g_x[i] = g_cat[(size_t)n * CATD + l * EMB + j] + g_vn[batch[n] * EMB + j];
    }
}

// ---------------- VN pooling ----------------
__global__ void k_pool(const int* __restrict__ batch) {
    __shared__ float s[VN * EMB];
    int tid = threadIdx.x;
    for (int i = tid; i < VN * EMB; i += 256) s[i] = 0.f;
    __syncthreads();
    int j = tid & 63, r = tid >> 6;
    for (int n = blockIdx.x * 4 + r; n < NCELL; n += gridDim.x * 4) {
        int b = batch[n];
        atomicAdd(&s[b * EMB + j], g_x[(size_t)n * EMB + j]);
    }
    __syncthreads();
    for (int i = tid; i < VN * EMB; i += 256) atomicAdd(&g_pool[i], s[i]);
}

// ---------------- fused net update: h_net = relu((net + Σ w·x[src]) @ W + b) ----------------
__global__ __launch_bounds__(256) void k_net_fused(const float* __restrict__ W,
                                                   const float* __restrict__ b) {
    __shared__ float sW[EMB * EMB];
    __shared__ float sb[EMB];
    int tid = threadIdx.x;
    for (int i = tid; i < EMB * EMB; i += 256) sW[i] = W[i];
    if (tid < EMB) sb[tid] = b[tid];
    __syncthreads();
    int lane = tid & 31;
    int netid = blockIdx.x * 8 + (tid >> 5);
    if (netid >= MNET) return;
    int p0 = g_off_net[netid], p1 = g_off_net[netid + 1];
    const float2* x2 = (const float2*)g_x;
    float2* net2 = (float2*)g_net;
    float2 acc = net2[(size_t)netid * 32 + lane];
    int p = p0;
    for (; p + 1 < p1; p += 2) {
        int2 e0 = g_csr_net[p], e1 = g_csr_net[p + 1];
        float2 v0 = x2[(size_t)e0.x * 32 + lane];
        float2 v1 = x2[(size_t)e1.x * 32 + lane];
        float w0 = __int_as_float(e0.y), w1 = __int_as_float(e1.y);
        acc.x += w0 * v0.x + w1 * v1.x;
        acc.y += w0 * v0.y + w1 * v1.y;
    }
    if (p < p1) {
        int2 e0 = g_csr_net[p];
        float2 v0 = x2[(size_t)e0.x * 32 + lane];
        float w0 = __int_as_float(e0.y);
        acc.x += w0 * v0.x; acc.y += w0 * v0.y;
    }
    // conv: out[j] = relu(b[j] + Σ_k acc_row[k]*W[k][j]), lane owns j=2l,2l+1
    const float2* sW2 = (const float2*)sW;
    float ox = sb[2 * lane], oy = sb[2 * lane + 1];
    #pragma unroll
    for (int k = 0; k < 32; k++) {
        float v0 = __shfl_sync(0xffffffffu, acc.x, k);
        float v1 = __shfl_sync(0xffffffffu, acc.y, k);
        float2 w0 = sW2[(2 * k) * 32 + lane];
        float2 w1 = sW2[(2 * k + 1) * 32 + lane];
        ox += v0 * w0.x + v1 * w1.x;
        oy += v0 * w0.y + v1 * w1.y;
    }
    net2[(size_t)netid * 32 + lane] = make_float2(fmaxf(ox, 0.f), fmaxf(oy, 0.f));
}

// ---------------- fused node update: h_node = relu((x + Σ ew·net[e]) @ W + b) -> cat ----------------
__global__ __launch_bounds__(256) void k_node_fused(const float* __restrict__ W,
                                                    const float* __restrict__ b, int l) {
    __shared__ float sW[EMB * EMB];
    __shared__ float sb[EMB];
    int tid = threadIdx.x;
    for (int i = tid; i < EMB * EMB; i += 256) sW[i] = W[i];
    if (tid < EMB) sb[tid] = b[tid];
    __syncthreads();
    int lane = tid & 31;
    int node = blockIdx.x * 8 + (tid >> 5);
    if (node >= NCELL) return;
    int p0 = g_off_node[node], p1 = g_off_node[node + 1];
    const float2* net2 = (const float2*)g_net;
    const float2* x2 = (const float2*)g_x;
    float2 acc = x2[(size_t)node * 32 + lane];
    int p = p0;
    for (; p + 1 < p1; p += 2) {
        int2 e0 = g_csr_node[p], e1 = g_csr_node[p + 1];
        float2 v0 = net2[(size_t)e0.x * 32 + lane];
        float2 v1 = net2[(size_t)e1.x * 32 + lane];
        float w0 = __int_as_float(e0.y), w1 = __int_as_float(e1.y);
        acc.x += w0 * v0.x + w1 * v1.x;
        acc.y += w0 * v0.y + w1 * v1.y;
    }
    if (p < p1) {
        int2 e0 = g_csr_node[p];
        float2 v0 = net2[(size_t)e0.x * 32 + lane];
        float w0 = __int_as_float(e0.y);
        acc.x += w0 * v0.x; acc.y += w0 * v0.y;
    }
    const float2* sW2 = (const float2*)sW;
    float ox = sb[2 * lane], oy = sb[2 * lane + 1];
    #pragma unroll
    for (int k = 0; k < 32; k++) {
        float v0 = __shfl_sync(0xffffffffu, acc.x, k);
        float v1 = __shfl_sync(0xffffffffu, acc.y, k);
        float2 w0 = sW2[(2 * k) * 32 + lane];
        float2 w1 = sW2[(2 * k + 1) * 32 + lane];
        ox += v0 * w0.x + v1 * w1.x;
        oy += v0 * w0.y + v1 * w1.y;
    }
    ((float2*)g_cat)[(size_t)node * 128 + (l + 1) * 32 + lane] =
        make_float2(fmaxf(ox, 0.f), fmaxf(oy, 0.f));
}

// ---------------- VN update ----------------
__global__ void k_vn(const float* __restrict__ w, const float* __restrict__ b) {
    int v = blockIdx.x, j = threadIdx.x;
    __shared__ float t[EMB];
    float c = fmaxf(g_cntvn[v], 1.f);
    t[j] = g_pool[v * EMB + j] / c + g_vn[v * EMB + j];
    __syncthreads();
    float acc = b[j];
    #pragma unroll
    for (int k = 0; k < EMB; k++) acc += t[k] * w[k * EMB + j];
    g_vn[v * EMB + j] += fmaxf(acc, 0.f);
}

// ---------------- head ----------------
__global__ __launch_bounds__(256) void k_head(
    const float* __restrict__ fc1w, const float* __restrict__ fc1b,
    const float* __restrict__ fc2w, const float* __restrict__ fc2b,
    const float* __restrict__ outw, const float* __restrict__ outb,
    const float* __restrict__ cat,
    float* __restrict__ nodes_out, float* __restrict__ ret_out) {
    __shared__ float As[32][64];
    __shared__ float Hs[32][257];
    __shared__ float rpart[32][8];
    int tid = threadIdx.x;
    int j = tid;
    size_t n0 = (size_t)blockIdx.x * 32;
    float acc[32];
    float bj = fc1b[j];
    #pragma unroll
    for (int i = 0; i < 32; i++) acc[i] = bj;

    for (int kc = 0; kc < 4; kc++) {
        __syncthreads();
        #pragma unroll
        for (int q = 0; q < 8; q++) {
            int idx = tid + q * 256;
            int i = idx >> 6, k = idx & 63;
            size_t row = n0 + i;
            As[i][k] = (row < NCELL) ? cat[row * CATD + kc * 64 + k] : 0.f;
        }
        __syncthreads();
        #pragma unroll
        for (int k = 0; k < 64; k++) {
            float bkj = fc1w[(kc * 64 + k) * 256 + j];
            #pragma unroll
            for (int i = 0; i < 32; i++) acc[i] += As[i][k] * bkj;
        }
    }
    #pragma unroll
    for (int i = 0; i < 32; i++) Hs[i][j] = fmaxf(acc[i], 0.f);
    __syncthreads();

    int i2 = tid >> 3, o = tid & 7;
    size_t row = n0 + i2;
    {
        float a = fc2b[o];
        #pragma unroll 8
        for (int jj = 0; jj < 256; jj++) a += Hs[i2][jj] * fc2w[jj * 8 + o];
        if (row < NCELL) nodes_out[row * OUTD + o] = fmaxf(a, 0.f);
    }
    {
        float a = 0.f;
        if (row < NCELL) {
            const float* crow = cat + row * CATD;
            #pragma unroll
            for (int jj = o * 32; jj < o * 32 + 32; jj++) a += crow[jj] * outw[jj];
        }
        rpart[i2][o] = a;
        __syncthreads();
        if (o == 0 && row < NCELL) {
            float s = outb[0];
            #pragma unroll
            for (int q = 0; q < 8; q++) s += rpart[i2][q];
            ret_out[row] = s;
        }
    }
}

// ---------------- launch ----------------
static inline int cdiv(long long a, long long b) { return (int)((a + b - 1) / b); }

extern "C" void kernel_launch(void* const* d_in, const int* in_sizes, int n_in,
                              void* d_out, int out_size) {
    const float* node_f     = (const float*)d_in[0];
    const float* net_f      = (const float*)d_in[1];
    const int*   sink_node  = (const int*)d_in[2];
    const int*   sink_net   = (const int*)d_in[3];
    const int*   src_node   = (const int*)d_in[4];
    const int*   src_net    = (const int*)d_in[5];
    const int*   batch      = (const int*)d_in[6];
    const float* w_node     = (const float*)d_in[8];
    const float* b_node     = (const float*)d_in[9];
    const float* w_net      = (const float*)d_in[10];
    const float* b_net      = (const float*)d_in[11];
    const float* vn_emb     = (const float*)d_in[12];
    const float* vn_mlp_w   = (const float*)d_in[13];
    const float* vn_mlp_b   = (const float*)d_in[14];
    const float* conv_net_w = (const float*)d_in[15];
    const float* conv_net_b = (const float*)d_in[16];
    const float* conv_node_w= (const float*)d_in[17];
    const float* conv_node_b= (const float*)d_in[18];
    const float* fc1_w      = (const float*)d_in[19];
    const float* fc1_b      = (const float*)d_in[20];
    const float* fc2_w      = (const float*)d_in[21];
    const float* fc2_b      = (const float*)d_in[22];
    const float* out_w      = (const float*)d_in[23];
    const float* out_b      = (const float*)d_in[24];

    int *p_cnt_n, *p_cnt_e, *p_cnt_comb, *p_off_net, *p_cur_net, *p_off_node, *p_cur_node;
    float *p_cat, *p_pool, *p_cntvn;
    cudaGetSymbolAddress((void**)&p_cnt_n, g_cnt_n);
    cudaGetSymbolAddress((void**)&p_cnt_e, g_cnt_e);
    cudaGetSymbolAddress((void**)&p_cnt_comb, g_cnt_comb);
    cudaGetSymbolAddress((void**)&p_off_net, g_off_net);
    cudaGetSymbolAddress((void**)&p_cur_net, g_cur_net);
    cudaGetSymbolAddress((void**)&p_off_node, g_off_node);
    cudaGetSymbolAddress((void**)&p_cur_node, g_cur_node);
    cudaGetSymbolAddress((void**)&p_cat, g_cat);
    cudaGetSymbolAddress((void**)&p_pool, g_pool);
    cudaGetSymbolAddress((void**)&p_cntvn, g_cntvn);

    // --- counts ---
    k_zeroi<<<cdiv(NCELL, 256), 256>>>(p_cnt_n, NCELL);
    k_zeroi<<<cdiv(MNET, 256), 256>>>(p_cnt_e, MNET);
    k_zeroi<<<cdiv(MNET, 256), 256>>>(p_cnt_comb, MNET);
    k_zerof<<<1, 64>>>(p_cntvn, VN);
    k_count_sink<<<cdiv(EKE, 256), 256>>>(sink_node, sink_net);
    k_count_src<<<cdiv(ESE, 256), 256>>>(src_net);
    k_addcnt<<<cdiv(MNET, 256), 256>>>();
    k_rsq_n<<<cdiv(NCELL, 256), 256>>>();
    k_rsq_e<<<cdiv(MNET, 256), 256>>>();
    k_ew<<<cdiv(EKE, 256), 256>>>(sink_node, sink_net);
    k_cnt<<<128, 256>>>(batch);

    // --- CSR by net (combined src+sink) ---
    {
        int nb = cdiv(MNET, 1024);
        k_scan1<<<nb, 256>>>(p_cnt_comb, MNET);
        k_scan2<<<1, 1024>>>(nb);
        k_scan3<<<nb, 256>>>(p_cnt_comb, MNET, p_off_net, p_cur_net);
        k_sentinel<<<1, 1>>>(p_off_net, MNET, ECOMB);
    }
    // --- CSR by node (sink edges) ---
    {
        int nb = cdiv(NCELL, 1024);
        k_scan1<<<nb, 256>>>(p_cnt_n, NCELL);
        k_scan2<<<1, 1024>>>(nb);
        k_scan3<<<nb, 256>>>(p_cnt_n, NCELL, p_off_node, p_cur_node);
        k_sentinel<<<1, 1>>>(p_off_node, NCELL, EKE);
    }
    k_scat_net_src<<<cdiv(ESE, 256), 256>>>(src_node, src_net);
    k_scat_net_sink<<<cdiv(EKE, 256), 256>>>(sink_node, sink_net);
    k_scat_node<<<cdiv(EKE, 256), 256>>>(sink_node, sink_net);

    // --- embeddings ---
    k_embed<<<cdiv(NCELL, 16), 256>>>(node_f, w_node, b_node, p_cat, NCELL, CATD);
    float* p_net; cudaGetSymbolAddress((void**)&p_net, g_net);
    k_embed<<<cdiv(MNET, 16), 256>>>(net_f, w_net, b_net, p_net, MNET, EMB);
    k_vninit<<<cdiv(VN * EMB, 256), 256>>>(vn_emb);

    // --- layers ---
    for (int l = 0; l < NL; l++) {
        k_make_x<<<cdiv((long long)NCELL * EMB, 256), 256>>>(batch, l);
        if (l < NL - 1) {
            k_zerof<<<cdiv(VN * EMB, 256), 256>>>(p_pool, VN * EMB);
            k_pool<<<128, 256>>>(batch);
        }
        k_net_fused<<<cdiv(MNET, 8), 256>>>(conv_net_w + l * 4096, conv_net_b + l * 64);
        k_node_fused<<<cdiv(NCELL, 8), 256>>>(conv_node_w + l * 4096, conv_node_b + l * 64, l);
        if (l < NL - 1)
            k_vn<<<VN, EMB>>>(vn_mlp_w + l * 4096, vn_mlp_b + l * 64);
    }

    // --- head ---
    float* nodes_out = (float*)d_out;
    float* ret_out = (float*)d_out + (size_t)NCELL * OUTD;
    k_head<<<cdiv(NCELL, 32), 256>>>(fc1_w, fc1_b, fc2_w, fc2_b, out_w, out_b,
                                     p_cat, nodes_out, ret_out);
}

// round 3
// speedup vs baseline: 1.6006x; 1.4488x over previous
#include <cuda_runtime.h>
#include <cstdint>

#define NCELL 500000
#define MNET  450000
#define EKE   2000000
#define ESE   500000
#define ECOMB (EKE + ESE)
#define EMB   64
#define VN    64
#define NL    3
#define CATD  256
#define OUTD  8

// ---------------- scratch ----------------
__device__ int   g_cnt_n[NCELL];
__device__ int   g_cnt_e[MNET];
__device__ int   g_cnt_comb[MNET];
__device__ float g_ew[EKE];
__device__ int   g_off_net[MNET + 1];
__device__ int   g_cur_net[MNET];
__device__ int   g_off_node[NCELL + 1];
__device__ int   g_cur_node[NCELL];
__device__ int2  g_csr_net[ECOMB];
__device__ int2  g_csr_node[EKE];
__device__ int   g_partial[1024];
__device__ float g_rsq_n[NCELL];
__device__ float g_rsq_e[MNET];
__device__ float g_cat[(size_t)NCELL * CATD];
__device__ float g_x[(size_t)NCELL * EMB];
__device__ float g_net[(size_t)MNET * EMB];
__device__ float g_vn[VN * EMB];
__device__ float g_pool[VN * EMB];
__device__ float g_cntvn[VN];

// ---------------- small helpers ----------------
__device__ __forceinline__ uint32_t f2tf32(float v) {
    uint32_t r; asm("cvt.rna.tf32.f32 %0, %1;" : "=r"(r) : "f"(v)); return r;
}
__device__ __forceinline__ void mma_tf32(float* c, uint32_t a0, uint32_t a1, uint32_t a2,
                                         uint32_t a3, uint32_t b0, uint32_t b1) {
    asm("mma.sync.aligned.m16n8k8.row.col.f32.tf32.tf32.f32 "
        "{%0,%1,%2,%3},{%4,%5,%6,%7},{%8,%9},{%0,%1,%2,%3};"
        : "+f"(c[0]), "+f"(c[1]), "+f"(c[2]), "+f"(c[3])
        : "r"(a0), "r"(a1), "r"(a2), "r"(a3), "r"(b0), "r"(b1));
}

// ---------------- utility kernels ----------------
__global__ void k_zeroi(int* p, int n) {
    int i = blockIdx.x * blockDim.x + threadIdx.x;
    if (i < n) p[i] = 0;
}
__global__ void k_zerof(float* p, int n) {
    int i = blockIdx.x * blockDim.x + threadIdx.x;
    if (i < n) p[i] = 0.f;
}
__global__ void k_count_sink(const int* __restrict__ sn, const int* __restrict__ se) {
    int i = blockIdx.x * blockDim.x + threadIdx.x;
    if (i < EKE) { atomicAdd(&g_cnt_n[sn[i]], 1); atomicAdd(&g_cnt_e[se[i]], 1); }
}
__global__ void k_count_src(const int* __restrict__ se) {
    int i = blockIdx.x * blockDim.x + threadIdx.x;
    if (i < ESE) atomicAdd(&g_cnt_comb[se[i]], 1);
}
__global__ void k_addcnt() {
    int i = blockIdx.x * blockDim.x + threadIdx.x;
    if (i < MNET) g_cnt_comb[i] += g_cnt_e[i];
}
__global__ void k_rsq_n() {
    int i = blockIdx.x * blockDim.x + threadIdx.x;
    if (i < NCELL) g_rsq_n[i] = rsqrtf(fmaxf((float)g_cnt_n[i], 1.f));
}
__global__ void k_rsq_e() {
    int i = blockIdx.x * blockDim.x + threadIdx.x;
    if (i < MNET) g_rsq_e[i] = rsqrtf(fmaxf((float)g_cnt_e[i], 1.f));
}
__global__ void k_ew(const int* __restrict__ sn, const int* __restrict__ se) {
    int i = blockIdx.x * blockDim.x + threadIdx.x;
    if (i < EKE) g_ew[i] = g_rsq_n[sn[i]] * g_rsq_e[se[i]];
}
__global__ void k_sentinel(int* a, int idx, int val) { a[idx] = val; }

// ---------------- 3-phase exclusive scan ----------------
__global__ void k_scan1(const int* __restrict__ cnt, int n) {
    __shared__ int s[256];
    int base = blockIdx.x * 1024, t = threadIdx.x;
    int sum = 0;
    #pragma unroll
    for (int q = 0; q < 4; q++) { int i = base + q * 256 + t; sum += (i < n) ? cnt[i] : 0; }
    s[t] = sum; __syncthreads();
    for (int st = 128; st > 0; st >>= 1) {
        if (t < st) s[t] += s[t + st];
        __syncthreads();
    }
    if (t == 0) g_partial[blockIdx.x] = s[0];
}
__global__ void k_scan2(int nb) {
    __shared__ int s[1024];
    int t = threadIdx.x;
    int v = (t < nb) ? g_partial[t] : 0;
    s[t] = v; __syncthreads();
    for (int st = 1; st < 1024; st <<= 1) {
        int a = (t >= st) ? s[t - st] : 0;
        __syncthreads();
        s[t] += a; __syncthreads();
    }
    if (t < nb) g_partial[t] = s[t] - v;
}
__global__ void k_scan3(const int* __restrict__ cnt, int n, int* __restrict__ off, int* __restrict__ cur) {
    __shared__ int s[256];
    int t = threadIdx.x, base = blockIdx.x * 1024;
    int v[4], sum = 0;
    #pragma unroll
    for (int q = 0; q < 4; q++) { int i = base + t * 4 + q; v[q] = (i < n) ? cnt[i] : 0; sum += v[q]; }
    s[t] = sum; __syncthreads();
    int mine = sum;
    for (int st = 1; st < 256; st <<= 1) {
        int a = (t >= st) ? s[t - st] : 0;
        __syncthreads();
        s[t] += a; __syncthreads();
    }
    int ex = s[t] - mine + g_partial[blockIdx.x];
    #pragma unroll
    for (int q = 0; q < 4; q++) {
        int i = base + t * 4 + q;
        if (i < n) { off[i] = ex; cur[i] = ex; ex += v[q]; }
    }
}

// ---------------- CSR scatters ----------------
__global__ void k_scat_net_src(const int* __restrict__ sn, const int* __restrict__ se) {
    int e = blockIdx.x * blockDim.x + threadIdx.x;
    if (e < ESE) {
        int pos = atomicAdd(&g_cur_net[se[e]], 1);
        g_csr_net[pos] = make_int2(sn[e], __float_as_int(1.f));
    }
}
__global__ void k_scat_net_sink(const int* __restrict__ sn, const int* __restrict__ se) {
    int e = blockIdx.x * blockDim.x + threadIdx.x;
    if (e < EKE) {
        int pos = atomicAdd(&g_cur_net[se[e]], 1);
        g_csr_net[pos] = make_int2(sn[e], __float_as_int(g_ew[e]));
    }
}
__global__ void k_scat_node(const int* __restrict__ sn, const int* __restrict__ se) {
    int e = blockIdx.x * blockDim.x + threadIdx.x;
    if (e < EKE) {
        int pos = atomicAdd(&g_cur_node[sn[e]], 1);
        g_csr_node[pos] = make_int2(se[e], __float_as_int(g_ew[e]));
    }
}

// ---------------- per-VN node counts ----------------
__global__ void k_cnt(const int* __restrict__ batch) {
    __shared__ float s[VN];
    int tid = threadIdx.x;
    if (tid < VN) s[tid] = 0.f;
    __syncthreads();
    for (int n = blockIdx.x * blockDim.x + tid; n < NCELL; n += gridDim.x * blockDim.x)
        atomicAdd(&s[batch[n]], 1.f);
    __syncthreads();
    if (tid < VN) atomicAdd(&g_cntvn[tid], s[tid]);
}
__global__ void k_vninit(const float* __restrict__ vn_emb) {
    int i = blockIdx.x * blockDim.x + threadIdx.x;
    if (i < VN * EMB) g_vn[i] = vn_emb[i & 63];
}

// ---------------- embedding ----------------
__global__ void k_embed(const float* __restrict__ feat,
                        const float* __restrict__ w, const float* __restrict__ b,
                        float* __restrict__ out, int nrows, int ostride) {
    __shared__ float s_w[16 * EMB];
    __shared__ float s_b[EMB];
    int tid = threadIdx.x;
    for (int i = tid; i < 16 * EMB; i += 256) s_w[i] = w[i];
    if (tid < EMB) s_b[tid] = b[tid];
    __syncthreads();
    int j = tid & 63, r = tid >> 6;
    int base = blockIdx.x * 16;
    for (int g = 0; g < 16; g += 4) {
        int row = base + g + r;
        if (row < nrows) {
            const float* f = feat + (size_t)row * 16;
            float acc = s_b[j];
            #pragma unroll
            for (int k = 0; k < 16; k++) acc += f[k] * s_w[k * EMB + j];
            out[(size_t)row * ostride + j] = fmaxf(acc, 0.f);
        }
    }
}

// ---------------- fused x = cat[l] + vn[batch]  (+ optional VN pooling) ----------------
__global__ void k_make_x_pool(const int* __restrict__ batch, int l, int doPool) {
    __shared__ float s[VN * EMB];
    int tid = threadIdx.x;
    if (doPool) {
        for (int i = tid; i < VN * EMB; i += 256) s[i] = 0.f;
        __syncthreads();
    }
    int j = tid & 63, r = tid >> 6;
    for (int n = blockIdx.x * 4 + r; n < NCELL; n += gridDim.x * 4) {
        int b = batch[n];
        float v = g_cat[(size_t)n * CATD + l * EMB + j] + g_vn[b * EMB + j];
        g_x[(size_t)n * EMB + j] = v;
        if (doPool) atomicAdd(&s[b * EMB + j], v);
    }
    if (doPool) {
        __syncthreads();
        for (int i = tid; i < VN * EMB; i += 256) atomicAdd(&g_pool[i], s[i]);
    }
}

// ---------------- fused net update ----------------
__global__ __launch_bounds__(256) void k_net_fused(const float* __restrict__ W,
                                                   const float* __restrict__ b) {
    __shared__ float sW[EMB * EMB];
    __shared__ float sb[EMB];
    int tid = threadIdx.x;
    for (int i = tid; i < EMB * EMB; i += 256) sW[i] = W[i];
    if (tid < EMB) sb[tid] = b[tid];
    __syncthreads();
    int lane = tid & 31;
    int netid = blockIdx.x * 8 + (tid >> 5);
    if (netid >= MNET) return;
    int p0 = g_off_net[netid], p1 = g_off_net[netid + 1];
    const float2* x2 = (const float2*)g_x;
    float2* net2 = (float2*)g_net;
    float2 acc = net2[(size_t)netid * 32 + lane];
    int p = p0;
    for (; p + 3 < p1; p += 4) {
        int2 e0 = g_csr_net[p], e1 = g_csr_net[p + 1], e2 = g_csr_net[p + 2], e3 = g_csr_net[p + 3];
        float2 v0 = x2[(size_t)e0.x * 32 + lane];
        float2 v1 = x2[(size_t)e1.x * 32 + lane];
        float2 v2 = x2[(size_t)e2.x * 32 + lane];
        float2 v3 = x2[(size_t)e3.x * 32 + lane];
        float w0 = __int_as_float(e0.y), w1 = __int_as_float(e1.y);
        float w2 = __int_as_float(e2.y), w3 = __int_as_float(e3.y);
        acc.x += w0 * v0.x + w1 * v1.x + w2 * v2.x + w3 * v3.x;
        acc.y += w0 * v0.y + w1 * v1.y + w2 * v2.y + w3 * v3.y;
    }
    for (; p < p1; p++) {
        int2 e0 = g_csr_net[p];
        float2 v0 = x2[(size_t)e0.x * 32 + lane];
        float w0 = __int_as_float(e0.y);
        acc.x += w0 * v0.x; acc.y += w0 * v0.y;
    }
    const float2* sW2 = (const float2*)sW;
    float ox = sb[2 * lane], oy = sb[2 * lane + 1];
    #pragma unroll
    for (int k = 0; k < 32; k++) {
        float v0 = __shfl_sync(0xffffffffu, acc.x, k);
        float v1 = __shfl_sync(0xffffffffu, acc.y, k);
        float2 w0 = sW2[(2 * k) * 32 + lane];
        float2 w1 = sW2[(2 * k + 1) * 32 + lane];
        ox += v0 * w0.x + v1 * w1.x;
        oy += v0 * w0.y + v1 * w1.y;
    }
    net2[(size_t)netid * 32 + lane] = make_float2(fmaxf(ox, 0.f), fmaxf(oy, 0.f));
}

// ---------------- fused node update ----------------
__global__ __launch_bounds__(256) void k_node_fused(const float* __restrict__ W,
                                                    const float* __restrict__ b, int l) {
    __shared__ float sW[EMB * EMB];
    __shared__ float sb[EMB];
    int tid = threadIdx.x;
    for (int i = tid; i < EMB * EMB; i += 256) sW[i] = W[i];
    if (tid < EMB) sb[tid] = b[tid];
    __syncthreads();
    int lane = tid & 31;
    int node = blockIdx.x * 8 + (tid >> 5);
    if (node >= NCELL) return;
    int p0 = g_off_node[node], p1 = g_off_node[node + 1];
    const float2* net2 = (const float2*)g_net;
    const float2* x2 = (const float2*)g_x;
    float2 acc = x2[(size_t)node * 32 + lane];
    int p = p0;
    for (; p + 3 < p1; p += 4) {
        int2 e0 = g_csr_node[p], e1 = g_csr_node[p + 1], e2 = g_csr_node[p + 2], e3 = g_csr_node[p + 3];
        float2 v0 = net2[(size_t)e0.x * 32 + lane];
        float2 v1 = net2[(size_t)e1.x * 32 + lane];
        float2 v2 = net2[(size_t)e2.x * 32 + lane];
        float2 v3 = net2[(size_t)e3.x * 32 + lane];
        float w0 = __int_as_float(e0.y), w1 = __int_as_float(e1.y);
        float w2 = __int_as_float(e2.y), w3 = __int_as_float(e3.y);
        acc.x += w0 * v0.x + w1 * v1.x + w2 * v2.x + w3 * v3.x;
        acc.y += w0 * v0.y + w1 * v1.y + w2 * v2.y + w3 * v3.y;
    }
    for (; p < p1; p++) {
        int2 e0 = g_csr_node[p];
        float2 v0 = net2[(size_t)e0.x * 32 + lane];
        float w0 = __int_as_float(e0.y);
        acc.x += w0 * v0.x; acc.y += w0 * v0.y;
    }
    const float2* sW2 = (const float2*)sW;
    float ox = sb[2 * lane], oy = sb[2 * lane + 1];
    #pragma unroll
    for (int k = 0; k < 32; k++) {
        float v0 = __shfl_sync(0xffffffffu, acc.x, k);
        float v1 = __shfl_sync(0xffffffffu, acc.y, k);
        float2 w0 = sW2[(2 * k) * 32 + lane];
        float2 w1 = sW2[(2 * k + 1) * 32 + lane];
        ox += v0 * w0.x + v1 * w1.x;
        oy += v0 * w0.y + v1 * w1.y;
    }
    ((float2*)g_cat)[(size_t)node * 128 + (l + 1) * 32 + lane] =
        make_float2(fmaxf(ox, 0.f), fmaxf(oy, 0.f));
}

// ---------------- VN update ----------------
__global__ void k_vn(const float* __restrict__ w, const float* __restrict__ b) {
    int v = blockIdx.x, j = threadIdx.x;
    __shared__ float t[EMB];
    float c = fmaxf(g_cntvn[v], 1.f);
    t[j] = g_pool[v * EMB + j] / c + g_vn[v * EMB + j];
    __syncthreads();
    float acc = b[j];
    #pragma unroll
    for (int k = 0; k < EMB; k++) acc += t[k] * w[k * EMB + j];
    g_vn[v * EMB + j] += fmaxf(acc, 0.f);
}

// ---------------- head (tf32 mma for fc1) ----------------
// block: 64 rows × 256 fc1-cols, 256 threads = 8 warps (4 along M × 2 along N)
#define AS_LD 68
#define BS_LD 260
#define HS_LD 264
#define DSMEM_HEAD ((64 * AS_LD + 64 * BS_LD) * 4)

__global__ __launch_bounds__(256) void k_head_mma(
    const float* __restrict__ fc1w, const float* __restrict__ fc1b,
    const float* __restrict__ fc2w, const float* __restrict__ fc2b,
    const float* __restrict__ outw, const float* __restrict__ outb,
    const float* __restrict__ cat,
    float* __restrict__ nodes_out, float* __restrict__ ret_out) {
    extern __shared__ float sm[];
    float* As = sm;                 // [64][AS_LD]
    float* Bs = sm + 64 * AS_LD;    // [64][BS_LD]
    float* Hs = sm;                 // [64][HS_LD] (aliases As/Bs after fc1)
    __shared__ float s_ow[CATD];
    __shared__ float s_fc2[8 * 256];   // o-major
    __shared__ float rpart4[64][4];

    int tid = threadIdx.x;
    int warp = tid >> 5, lane = tid & 31;
    int gid = lane >> 2, tig = lane & 3;
    int mrow0 = (warp >> 1) * 16;
    int ncol0 = (warp & 1) * 128;
    size_t n0 = (size_t)blockIdx.x * 64;

    // stage out_w, fc2w(o-major); init rpart
    if (tid < CATD) s_ow[tid] = outw[tid];
    for (int i = tid; i < 2048; i += 256) {
        int o = i >> 8, jj = i & 255;
        s_fc2[o * 256 + jj] = fc2w[jj * 8 + o];
    }
    { int r = tid >> 2, q = tid & 3; rpart4[r][q] = 0.f; }

    float c[16][4];
    #pragma unroll
    for (int nt = 0; nt < 16; nt++)
        #pragma unroll
        for (int q = 0; q < 4; q++) c[nt][q] = 0.f;

    for (int kc = 0; kc < 4; kc++) {
        __syncthreads();
        // stage A: 64x64 (float4)
        #pragma unroll
        for (int q = 0; q < 4; q++) {
            int idx = q * 256 + tid;          // 0..1023 float4s
            int r = idx >> 4, k4 = idx & 15;
            size_t row = n0 + r;
            float4 v = (row < NCELL)
                ? *(const float4*)(cat + row * CATD + kc * 64 + k4 * 4)
                : make_float4(0.f, 0.f, 0.f, 0.f);
            *(float4*)(As + r * AS_LD + k4 * 4) = v;
        }
        // stage B: 64x256 (float4)
        #pragma unroll
        for (int q = 0; q < 16; q++) {
            int idx = q * 256 + tid;          // 0..4095 float4s
            int r = idx >> 6, j4 = idx & 63;
            float4 v = *(const float4*)(fc1w + (size_t)(kc * 64 + r) * 256 + j4 * 4);
            *(float4*)(Bs + r * BS_LD + j4 * 4) = v;
        }
        __syncthreads();
        // ret partial from staged A
        {
            int r = tid >> 2, q = tid & 3;
            float a = 0.f;
            #pragma unroll
            for (int kk = 0; kk < 16; kk++)
                a += As[r * AS_LD + q * 16 + kk] * s_ow[kc * 64 + q * 16 + kk];
            rpart4[r][q] += a;
        }
        // mma over 8 k-steps
        #pragma unroll
        for (int kk = 0; kk < 8; kk++) {
            int kb = kk * 8;
            uint32_t a0 = f2tf32(As[(mrow0 + gid) * AS_LD + kb + tig]);
            uint32_t a1 = f2tf32(As[(mrow0 + gid + 8) * AS_LD + kb + tig]);
            uint32_t a2 = f2tf32(As[(mrow0 + gid) * AS_LD + kb + tig + 4]);
            uint32_t a3 = f2tf32(As[(mrow0 + gid + 8) * AS_LD + kb + tig + 4]);
            #pragma unroll
            for (int nt = 0; nt < 16; nt++) {
                int col = ncol0 + nt * 8 + gid;
                uint32_t b0 = f2tf32(Bs[(kb + tig) * BS_LD + col]);
                uint32_t b1 = f2tf32(Bs[(kb + tig + 4) * BS_LD + col]);
                mma_tf32(c[nt], a0, a1, a2, a3, b0, b1);
            }
        }
    }
    __syncthreads();
    // write Hs = relu(c + fc1b)
    #pragma unroll
    for (int nt = 0; nt < 16; nt++) {
        int col0 = ncol0 + nt * 8 + 2 * tig;
        float bb0 = fc1b[col0], bb1 = fc1b[col0 + 1];
        Hs[(mrow0 + gid) * HS_LD + col0]     = fmaxf(c[nt][0] + bb0, 0.f);
        Hs[(mrow0 + gid) * HS_LD + col0 + 1] = fmaxf(c[nt][1] + bb1, 0.f);
        Hs[(mrow0 + gid + 8) * HS_LD + col0]     = fmaxf(c[nt][2] + bb0, 0.f);
        Hs[(mrow0 + gid + 8) * HS_LD + col0 + 1] = fmaxf(c[nt][3] + bb1, 0.f);
    }
    __syncthreads();
    // fc2 (fp32, float4) : 512 (row,out) pairs, 2 per thread
    #pragma unroll
    for (int pp = 0; pp < 2; pp++) {
        int p = tid + pp * 256;
        int r = p >> 3, o = p & 7;
        size_t row = n0 + r;
        float a = fc2b[o];
        const float4* h4 = (const float4*)(Hs + r * HS_LD);
        const float4* w4 = (const float4*)(s_fc2 + o * 256);
        #pragma unroll 8
        for (int jj = 0; jj < 64; jj++) {
            float4 h = h4[jj], w = w4[jj];
            a += h.x * w.x + h.y * w.y + h.z * w.z + h.w * w.w;
        }
        if (row < NCELL) nodes_out[row * OUTD + o] = fmaxf(a, 0.f);
    }
    // ret
    if (tid < 64) {
        size_t row = n0 + tid;
        if (row < NCELL) {
            float s = outb[0] + rpart4[tid][0] + rpart4[tid][1] + rpart4[tid][2] + rpart4[tid][3];
            ret_out[row] = s;
        }
    }
}

// ---------------- launch ----------------
static inline int cdiv(long long a, long long b) { return (int)((a + b - 1) / b); }

extern "C" void kernel_launch(void* const* d_in, const int* in_sizes, int n_in,
                              void* d_out, int out_size) {
    const float* node_f     = (const float*)d_in[0];
    const float* net_f      = (const float*)d_in[1];
    const int*   sink_node  = (const int*)d_in[2];
    const int*   sink_net   = (const int*)d_in[3];
    const int*   src_node   = (const int*)d_in[4];
    const int*   src_net    = (const int*)d_in[5];
    const int*   batch      = (const int*)d_in[6];
    const float* w_node     = (const float*)d_in[8];
    const float* b_node     = (const float*)d_in[9];
    const float* w_net      = (const float*)d_in[10];
    const float* b_net      = (const float*)d_in[11];
    const float* vn_emb     = (const float*)d_in[12];
    const float* vn_mlp_w   = (const float*)d_in[13];
    const float* vn_mlp_b   = (const float*)d_in[14];
    const float* conv_net_w = (const float*)d_in[15];
    const float* conv_net_b = (const float*)d_in[16];
    const float* conv_node_w= (const float*)d_in[17];
    const float* conv_node_b= (const float*)d_in[18];
    const float* fc1_w      = (const float*)d_in[19];
    const float* fc1_b      = (const float*)d_in[20];
    const float* fc2_w      = (const float*)d_in[21];
    const float* fc2_b      = (const float*)d_in[22];
    const float* out_w      = (const float*)d_in[23];
    const float* out_b      = (const float*)d_in[24];

    static bool attr_done = false;
    if (!attr_done) {
        cudaFuncSetAttribute(k_head_mma, cudaFuncAttributeMaxDynamicSharedMemorySize, DSMEM_HEAD);
        attr_done = true;
    }

    int *p_cnt_n, *p_cnt_e, *p_cnt_comb, *p_off_net, *p_cur_net, *p_off_node, *p_cur_node;
    float *p_cat, *p_pool, *p_cntvn, *p_net;
    cudaGetSymbolAddress((void**)&p_cnt_n, g_cnt_n);
    cudaGetSymbolAddress((void**)&p_cnt_e, g_cnt_e);
    cudaGetSymbolAddress((void**)&p_cnt_comb, g_cnt_comb);
    cudaGetSymbolAddress((void**)&p_off_net, g_off_net);
    cudaGetSymbolAddress((void**)&p_cur_net, g_cur_net);
    cudaGetSymbolAddress((void**)&p_off_node, g_off_node);
    cudaGetSymbolAddress((void**)&p_cur_node, g_cur_node);
    cudaGetSymbolAddress((void**)&p_cat, g_cat);
    cudaGetSymbolAddress((void**)&p_pool, g_pool);
    cudaGetSymbolAddress((void**)&p_cntvn, g_cntvn);
    cudaGetSymbolAddress((void**)&p_net, g_net);

    // --- counts ---
    k_zeroi<<<cdiv(NCELL, 256), 256>>>(p_cnt_n, NCELL);
    k_zeroi<<<cdiv(MNET, 256), 256>>>(p_cnt_e, MNET);
    k_zeroi<<<cdiv(MNET, 256), 256>>>(p_cnt_comb, MNET);
    k_zerof<<<1, 64>>>(p_cntvn, VN);
    k_count_sink<<<cdiv(EKE, 256), 256>>>(sink_node, sink_net);
    k_count_src<<<cdiv(ESE, 256), 256>>>(src_net);
    k_addcnt<<<cdiv(MNET, 256), 256>>>();
    k_rsq_n<<<cdiv(NCELL, 256), 256>>>();
    k_rsq_e<<<cdiv(MNET, 256), 256>>>();
    k_ew<<<cdiv(EKE, 256), 256>>>(sink_node, sink_net);
    k_cnt<<<128, 256>>>(batch);

    // --- CSR by net ---
    {
        int nb = cdiv(MNET, 1024);
        k_scan1<<<nb, 256>>>(p_cnt_comb, MNET);
        k_scan2<<<1, 1024>>>(nb);
        k_scan3<<<nb, 256>>>(p_cnt_comb, MNET, p_off_net, p_cur_net);
        k_sentinel<<<1, 1>>>(p_off_net, MNET, ECOMB);
    }
    // --- CSR by node ---
    {
        int nb = cdiv(NCELL, 1024);
        k_scan1<<<nb, 256>>>(p_cnt_n, NCELL);
        k_scan2<<<1, 1024>>>(nb);
        k_scan3<<<nb, 256>>>(p_cnt_n, NCELL, p_off_node, p_cur_node);
        k_sentinel<<<1, 1>>>(p_off_node, NCELL, EKE);
    }
    k_scat_net_src<<<cdiv(ESE, 256), 256>>>(src_node, src_net);
    k_scat_net_sink<<<cdiv(EKE, 256), 256>>>(sink_node, sink_net);
    k_scat_node<<<cdiv(EKE, 256), 256>>>(sink_node, sink_net);

    // --- embeddings ---
    k_embed<<<cdiv(NCELL, 16), 256>>>(node_f, w_node, b_node, p_cat, NCELL, CATD);
    k_embed<<<cdiv(MNET, 16), 256>>>(net_f, w_net, b_net, p_net, MNET, EMB);
    k_vninit<<<cdiv(VN * EMB, 256), 256>>>(vn_emb);

    // --- layers ---
    for (int l = 0; l < NL; l++) {
        int doPool = (l < NL - 1) ? 1 : 0;
        if (doPool) k_zerof<<<cdiv(VN * EMB, 256), 256>>>(p_pool, VN * EMB);
        k_make_x_pool<<<512, 256>>>(batch, l, doPool);
        k_net_fused<<<cdiv(MNET, 8), 256>>>(conv_net_w + l * 4096, conv_net_b + l * 64);
        k_node_fused<<<cdiv(NCELL, 8), 256>>>(conv_node_w + l * 4096, conv_node_b + l * 64, l);
        if (doPool)
            k_vn<<<VN, EMB>>>(vn_mlp_w + l * 4096, vn_mlp_b + l * 64);
    }

    // --- head ---
    float* nodes_out = (float*)d_out;
    float* ret_out = (float*)d_out + (size_t)NCELL * OUTD;
    k_head_mma<<<cdiv(NCELL, 64), 256, DSMEM_HEAD>>>(fc1_w, fc1_b, fc2_w, fc2_b,
                                                     out_w, out_b, p_cat, nodes_out, ret_out);
}

// round 5
// speedup vs baseline: 1.9042x; 1.1896x over previous
#include <cuda_runtime.h>
#include <cstdint>

#define NCELL 500000
#define MNET  450000
#define EKE   2000000
#define ESE   500000
#define ECOMB (EKE + ESE)
#define EMB   64
#define VN    64
#define NL    3
#define CATD  256
#define OUTD  8

// ---------------- scratch ----------------
__device__ int   g_cnt_n[NCELL];
__device__ int   g_cnt_e[MNET];
__device__ int   g_cnt_comb[MNET];
__device__ int   g_off_net[MNET + 1];
__device__ int   g_cur_net[MNET];
__device__ int   g_off_node[NCELL + 1];
__device__ int   g_cur_node[NCELL];
__device__ int2  g_csr_net[ECOMB];
__device__ int2  g_csr_node[EKE];
__device__ int   g_partial[1024];
__device__ float g_rsq_n[NCELL];
__device__ float g_rsq_e[MNET];
__device__ float g_cat[(size_t)NCELL * CATD];
__device__ float g_net[(size_t)MNET * EMB];
__device__ float g_vn[VN * EMB];
__device__ float g_pool[VN * EMB];
__device__ float g_cntvn[VN];

// ---------------- helpers ----------------
__device__ __forceinline__ uint32_t f2tf32(float v) {
    uint32_t r; asm("cvt.rna.tf32.f32 %0, %1;" : "=r"(r) : "f"(v)); return r;
}
__device__ __forceinline__ void split_tf32(float v, uint32_t& hi, uint32_t& lo) {
    hi = f2tf32(v);
    lo = f2tf32(v - __uint_as_float(hi));
}
__device__ __forceinline__ void mma_tf32(float* c, uint32_t a0, uint32_t a1, uint32_t a2,
                                         uint32_t a3, uint32_t b0, uint32_t b1) {
    asm("mma.sync.aligned.m16n8k8.row.col.f32.tf32.tf32.f32 "
        "{%0,%1,%2,%3},{%4,%5,%6,%7},{%8,%9},{%0,%1,%2,%3};"
        : "+f"(c[0]), "+f"(c[1]), "+f"(c[2]), "+f"(c[3])
        : "r"(a0), "r"(a1), "r"(a2), "r"(a3), "r"(b0), "r"(b1));
}

// ---------------- utility kernels ----------------
__global__ void k_zeroi(int* p, int n) {
    int i = blockIdx.x * blockDim.x + threadIdx.x;
    if (i < n) p[i] = 0;
}
__global__ void k_zerof(float* p, int n) {
    int i = blockIdx.x * blockDim.x + threadIdx.x;
    if (i < n) p[i] = 0.f;
}
__global__ void k_count_sink(const int* __restrict__ sn, const int* __restrict__ se) {
    int i = blockIdx.x * blockDim.x + threadIdx.x;
    if (i < EKE) { atomicAdd(&g_cnt_n[sn[i]], 1); atomicAdd(&g_cnt_e[se[i]], 1); }
}
__global__ void k_count_src(const int* __restrict__ se) {
    int i = blockIdx.x * blockDim.x + threadIdx.x;
    if (i < ESE) atomicAdd(&g_cnt_comb[se[i]], 1);
}
__global__ void k_addcnt() {
    int i = blockIdx.x * blockDim.x + threadIdx.x;
    if (i < MNET) g_cnt_comb[i] += g_cnt_e[i];
}
__global__ void k_rsq_n() {
    int i = blockIdx.x * blockDim.x + threadIdx.x;
    if (i < NCELL) g_rsq_n[i] = rsqrtf(fmaxf((float)g_cnt_n[i], 1.f));
}
__global__ void k_rsq_e() {
    int i = blockIdx.x * blockDim.x + threadIdx.x;
    if (i < MNET) g_rsq_e[i] = rsqrtf(fmaxf((float)g_cnt_e[i], 1.f));
}
__global__ void k_sentinel(int* a, int idx, int val) { a[idx] = val; }

// ---------------- 3-phase exclusive scan ----------------
__global__ void k_scan1(const int* __restrict__ cnt, int n) {
    __shared__ int s[256];
    int base = blockIdx.x * 1024, t = threadIdx.x;
    int sum = 0;
    #pragma unroll
    for (int q = 0; q < 4; q++) { int i = base + q * 256 + t; sum += (i < n) ? cnt[i] : 0; }
    s[t] = sum; __syncthreads();
    for (int st = 128; st > 0; st >>= 1) {
        if (t < st) s[t] += s[t + st];
        __syncthreads();
    }
    if (t == 0) g_partial[blockIdx.x] = s[0];
}
__global__ void k_scan2(int nb) {
    __shared__ int s[1024];
    int t = threadIdx.x;
    int v = (t < nb) ? g_partial[t] : 0;
    s[t] = v; __syncthreads();
    for (int st = 1; st < 1024; st <<= 1) {
        int a = (t >= st) ? s[t - st] : 0;
        __syncthreads();
        s[t] += a; __syncthreads();
    }
    if (t < nb) g_partial[t] = s[t] - v;
}
__global__ void k_scan3(const int* __restrict__ cnt, int n, int* __restrict__ off, int* __restrict__ cur) {
    __shared__ int s[256];
    int t = threadIdx.x, base = blockIdx.x * 1024;
    int v[4], sum = 0;
    #pragma unroll
    for (int q = 0; q < 4; q++) { int i = base + t * 4 + q; v[q] = (i < n) ? cnt[i] : 0; sum += v[q]; }
    s[t] = sum; __syncthreads();
    int mine = sum;
    for (int st = 1; st < 256; st <<= 1) {
        int a = (t >= st) ? s[t - st] : 0;
        __syncthreads();
        s[t] += a; __syncthreads();
    }
    int ex = s[t] - mine + g_partial[blockIdx.x];
    #pragma unroll
    for (int q = 0; q < 4; q++) {
        int i = base + t * 4 + q;
        if (i < n) { off[i] = ex; cur[i] = ex; ex += v[q]; }
    }
}

// ---------------- CSR scatters (ew computed inline) ----------------
__global__ void k_scat_net_src(const int* __restrict__ sn, const int* __restrict__ se) {
    int e = blockIdx.x * blockDim.x + threadIdx.x;
    if (e < ESE) {
        int pos = atomicAdd(&g_cur_net[se[e]], 1);
        g_csr_net[pos] = make_int2(sn[e], __float_as_int(1.f));
    }
}
__global__ void k_scat_net_sink(const int* __restrict__ sn, const int* __restrict__ se) {
    int e = blockIdx.x * blockDim.x + threadIdx.x;
    if (e < EKE) {
        int node = sn[e], net = se[e];
        float ew = g_rsq_n[node] * g_rsq_e[net];
        int pos = atomicAdd(&g_cur_net[net], 1);
        g_csr_net[pos] = make_int2(node, __float_as_int(ew));
    }
}
__global__ void k_scat_node(const int* __restrict__ sn, const int* __restrict__ se) {
    int e = blockIdx.x * blockDim.x + threadIdx.x;
    if (e < EKE) {
        int node = sn[e], net = se[e];
        float ew = g_rsq_n[node] * g_rsq_e[net];
        int pos = atomicAdd(&g_cur_node[node], 1);
        g_csr_node[pos] = make_int2(net, __float_as_int(ew));
    }
}

// ---------------- per-VN node counts ----------------
__global__ void k_cnt(const int* __restrict__ batch) {
    __shared__ float s[VN];
    int tid = threadIdx.x;
    if (tid < VN) s[tid] = 0.f;
    __syncthreads();
    for (int n = blockIdx.x * blockDim.x + tid; n < NCELL; n += gridDim.x * blockDim.x)
        atomicAdd(&s[batch[n]], 1.f);
    __syncthreads();
    if (tid < VN) atomicAdd(&g_cntvn[tid], s[tid]);
}
__global__ void k_vninit(const float* __restrict__ vn_emb) {
    int i = blockIdx.x * blockDim.x + threadIdx.x;
    if (i < VN * EMB) g_vn[i] = vn_emb[i & 63];
}

// ---------------- embedding ----------------
__global__ void k_embed(const float* __restrict__ feat,
                        const float* __restrict__ w, const float* __restrict__ b,
                        float* __restrict__ out, int nrows, int ostride) {
    __shared__ float s_w[16 * EMB];
    __shared__ float s_b[EMB];
    int tid = threadIdx.x;
    for (int i = tid; i < 16 * EMB; i += 256) s_w[i] = w[i];
    if (tid < EMB) s_b[tid] = b[tid];
    __syncthreads();
    int j = tid & 63, r = tid >> 6;
    int base = blockIdx.x * 16;
    for (int g = 0; g < 16; g += 4) {
        int row = base + g + r;
        if (row < nrows) {
            const float* f = feat + (size_t)row * 16;
            float acc = s_b[j];
            #pragma unroll
            for (int k = 0; k < 16; k++) acc += f[k] * s_w[k * EMB + j];
            out[(size_t)row * ostride + j] = fmaxf(acc, 0.f);
        }
    }
}

// ---------------- VN pooling directly from cat (pool = seg(cat_l, batch)) ----------------
__global__ void k_pool_cat(const int* __restrict__ batch, int l) {
    __shared__ float s[VN * EMB];
    int tid = threadIdx.x;
    for (int i = tid; i < VN * EMB; i += 256) s[i] = 0.f;
    __syncthreads();
    int j = tid & 63, r = tid >> 6;
    for (int n = blockIdx.x * 4 + r; n < NCELL; n += gridDim.x * 4) {
        int b = batch[n];
        atomicAdd(&s[b * EMB + j], g_cat[(size_t)n * CATD + l * EMB + j]);
    }
    __syncthreads();
    for (int i = tid; i < VN * EMB; i += 256) atomicAdd(&g_pool[i], s[i]);
}

// ---------------- VN update: vn += relu(((pool + cnt*vn)/max(cnt,1) + vn) @ W + b) ----------------
__global__ void k_vn(const float* __restrict__ w, const float* __restrict__ b) {
    int v = blockIdx.x, j = threadIdx.x;
    __shared__ float t[EMB];
    float cnt = g_cntvn[v];
    float vv = g_vn[v * EMB + j];
    t[j] = (g_pool[v * EMB + j] + cnt * vv) / fmaxf(cnt, 1.f) + vv;
    __syncthreads();
    float acc = b[j];
    #pragma unroll
    for (int k = 0; k < EMB; k++) acc += t[k] * w[k * EMB + j];
    g_vn[v * EMB + j] = vv + fmaxf(acc, 0.f);
}

// =====================================================================
// Fused gather + 3xTF32 mma conv kernels.
// Block = 256 threads (8 warps), processes 64 rows.
// smem layout (dynamic): As[64*68] | Ws[64*68] | vns[64*64] | sb[64]
// =====================================================================
#define CLD 68
#define DSMEM_CONV ((64 * CLD + 64 * CLD + VN * EMB + EMB) * 4)

// gather: acc = init_row + sum_e w_e * (cat[src,l] + vn[batch[src]])   (net pass)
//         acc = (cat[node,l] + vn[batch[node]]) + sum_e w_e * net[e]   (node pass)
// then   out = relu(acc @ W + b)

__device__ __forceinline__ void conv_mma_epilogue(
    float* As, float* Ws, const float* sb,
    int tid, long long row0, int nrows, float* __restrict__ outbuf,
    int ostride4, int ooff4)   // out float4 index: row*ostride4 + ooff4 + c4
{
    int warp = tid >> 5, lane = tid & 31;
    int gid = lane >> 2, tig = lane & 3;
    int mrow0 = (warp >> 1) * 16;
    int ncol0 = (warp & 1) * 32;

    float c[4][4];
    #pragma unroll
    for (int nt = 0; nt < 4; nt++)
        #pragma unroll
        for (int q = 0; q < 4; q++) c[nt][q] = 0.f;

    #pragma unroll
    for (int kk = 0; kk < 8; kk++) {
        int kb = kk * 8;
        uint32_t ah0, al0, ah1, al1, ah2, al2, ah3, al3;
        split_tf32(As[(mrow0 + gid) * CLD + kb + tig], ah0, al0);
        split_tf32(As[(mrow0 + gid + 8) * CLD + kb + tig], ah1, al1);
        split_tf32(As[(mrow0 + gid) * CLD + kb + tig + 4], ah2, al2);
        split_tf32(As[(mrow0 + gid + 8) * CLD + kb + tig + 4], ah3, al3);
        #pragma unroll
        for (int nt = 0; nt < 4; nt++) {
            int col = ncol0 + nt * 8 + gid;
            uint32_t bh0, bl0, bh1, bl1;
            split_tf32(Ws[(kb + tig) * CLD + col], bh0, bl0);
            split_tf32(Ws[(kb + tig + 4) * CLD + col], bh1, bl1);
            mma_tf32(c[nt], ah0, ah1, ah2, ah3, bh0, bh1);
            mma_tf32(c[nt], ah0, ah1, ah2, ah3, bl0, bl1);
            mma_tf32(c[nt], al0, al1, al2, al3, bh0, bh1);
        }
    }
    __syncthreads();   // all mma reads of As/Ws done
    // write relu(c + b) back into As (reused as H)
    #pragma unroll
    for (int nt = 0; nt < 4; nt++) {
        int col0 = ncol0 + nt * 8 + 2 * tig;
        float b0 = sb[col0], b1 = sb[col0 + 1];
        As[(mrow0 + gid) * CLD + col0]     = fmaxf(c[nt][0] + b0, 0.f);
        As[(mrow0 + gid) * CLD + col0 + 1] = fmaxf(c[nt][1] + b1, 0.f);
        As[(mrow0 + gid + 8) * CLD + col0]     = fmaxf(c[nt][2] + b0, 0.f);
        As[(mrow0 + gid + 8) * CLD + col0 + 1] = fmaxf(c[nt][3] + b1, 0.f);
    }
    __syncthreads();
    // coalesced float4 writeout
    #pragma unroll
    for (int q = 0; q < 4; q++) {
        int idx = q * 256 + tid;       // 0..1023 float4s
        int r = idx >> 4, c4 = idx & 15;
        long long row = row0 + r;
        if (row < nrows) {
            float4 v = *(const float4*)(As + r * CLD + c4 * 4);
            ((float4*)outbuf)[row * ostride4 + ooff4 + c4] = v;
        }
    }
}

__global__ __launch_bounds__(256) void k_net_mma(
    const float* __restrict__ W, const float* __restrict__ b,
    const int* __restrict__ batch, int l) {
    extern __shared__ float sm[];
    float* As = sm;
    float* Ws = sm + 64 * CLD;
    float* vns = sm + 128 * CLD;
    float* sb = vns + VN * EMB;
    int tid = threadIdx.x;
    for (int i = tid; i < EMB * EMB; i += 256) Ws[(i >> 6) * CLD + (i & 63)] = W[i];
    for (int i = tid; i < VN * EMB; i += 256) vns[i] = g_vn[i];
    if (tid < EMB) sb[tid] = b[tid];
    __syncthreads();

    int warp = tid >> 5, lane = tid & 31;
    long long row0 = (long long)blockIdx.x * 64;
    const float2* cat2 = (const float2*)g_cat;
    const float2* net2 = (const float2*)g_net;
    const float2* vn2 = (const float2*)vns;

    for (int q = 0; q < 8; q++) {
        int r = warp * 8 + q;
        long long netid = row0 + r;
        float2 acc = make_float2(0.f, 0.f);
        if (netid < MNET) {
            acc = net2[netid * 32 + lane];
            int p0 = g_off_net[netid], p1 = g_off_net[netid + 1];
            int p = p0;
            for (; p + 1 < p1; p += 2) {
                int2 e0 = g_csr_net[p], e1 = g_csr_net[p + 1];
                int b0 = batch[e0.x], b1 = batch[e1.x];
                float2 v0 = cat2[(size_t)e0.x * 128 + l * 32 + lane];
                float2 v1 = cat2[(size_t)e1.x * 128 + l * 32 + lane];
                float2 u0 = vn2[b0 * 32 + lane];
                float2 u1 = vn2[b1 * 32 + lane];
                float w0 = __int_as_float(e0.y), w1 = __int_as_float(e1.y);
                acc.x += w0 * (v0.x + u0.x) + w1 * (v1.x + u1.x);
                acc.y += w0 * (v0.y + u0.y) + w1 * (v1.y + u1.y);
            }
            if (p < p1) {
                int2 e0 = g_csr_net[p];
                int b0 = batch[e0.x];
                float2 v0 = cat2[(size_t)e0.x * 128 + l * 32 + lane];
                float2 u0 = vn2[b0 * 32 + lane];
                float w0 = __int_as_float(e0.y);
                acc.x += w0 * (v0.x + u0.x);
                acc.y += w0 * (v0.y + u0.y);
            }
        }
        *(float2*)(As + r * CLD + 2 * lane) = acc;
    }
    __syncthreads();
    conv_mma_epilogue(As, Ws, sb, tid, row0, MNET, (float*)g_net, 16, 0);
}

__global__ __launch_bounds__(256) void k_node_mma(
    const float* __restrict__ W, const float* __restrict__ b,
    const int* __restrict__ batch, int l) {
    extern __shared__ float sm[];
    float* As = sm;
    float* Ws = sm + 64 * CLD;
    float* vns = sm + 128 * CLD;
    float* sb = vns + VN * EMB;
    int tid = threadIdx.x;
    for (int i = tid; i < EMB * EMB; i += 256) Ws[(i >> 6) * CLD + (i & 63)] = W[i];
    for (int i = tid; i < VN * EMB; i += 256) vns[i] = g_vn[i];
    if (tid < EMB) sb[tid] = b[tid];
    __syncthreads();

    int warp = tid >> 5, lane = tid & 31;
    long long row0 = (long long)blockIdx.x * 64;
    const float2* cat2 = (const float2*)g_cat;
    const float2* net2 = (const float2*)g_net;
    const float2* vn2 = (const float2*)vns;

    for (int q = 0; q < 8; q++) {
        int r = warp * 8 + q;
        long long node = row0 + r;
        float2 acc = make_float2(0.f, 0.f);
        if (node < NCELL) {
            int bb = batch[node];
            float2 v = cat2[node * 128 + l * 32 + lane];
            float2 u = vn2[bb * 32 + lane];
            acc.x = v.x + u.x; acc.y = v.y + u.y;
            int p0 = g_off_node[node], p1 = g_off_node[node + 1];
            int p = p0;
            for (; p + 1 < p1; p += 2) {
                int2 e0 = g_csr_node[p], e1 = g_csr_node[p + 1];
                float2 v0 = net2[(size_t)e0.x * 32 + lane];
                float2 v1 = net2[(size_t)e1.x * 32 + lane];
                float w0 = __int_as_float(e0.y), w1 = __int_as_float(e1.y);
                acc.x += w0 * v0.x + w1 * v1.x;
                acc.y += w0 * v0.y + w1 * v1.y;
            }
            if (p < p1) {
                int2 e0 = g_csr_node[p];
                float2 v0 = net2[(size_t)e0.x * 32 + lane];
                float w0 = __int_as_float(e0.y);
                acc.x += w0 * v0.x; acc.y += w0 * v0.y;
            }
        }
        *(float2*)(As + r * CLD + 2 * lane) = acc;
    }
    __syncthreads();
    conv_mma_epilogue(As, Ws, sb, tid, row0, NCELL, (float*)g_cat, 64, (l + 1) * 16);
}

// ---------------- head (tf32 mma for fc1) ----------------
#define AS_LD 68
#define BS_LD 260
#define HS_LD 264
#define DSMEM_HEAD ((64 * AS_LD + 64 * BS_LD) * 4)

__global__ __launch_bounds__(256) void k_head_mma(
    const float* __restrict__ fc1w, const float* __restrict__ fc1b,
    const float* __restrict__ fc2w, const float* __restrict__ fc2b,
    const float* __restrict__ outw, const float* __restrict__ outb,
    const float* __restrict__ cat,
    float* __restrict__ nodes_out, float* __restrict__ ret_out) {
    extern __shared__ float sm[];
    float* As = sm;
    float* Bs = sm + 64 * AS_LD;
    float* Hs = sm;
    __shared__ float s_ow[CATD];
    __shared__ float s_fc2[8 * 256];
    __shared__ float rpart4[64][4];

    int tid = threadIdx.x;
    int warp = tid >> 5, lane = tid & 31;
    int gid = lane >> 2, tig = lane & 3;
    int mrow0 = (warp >> 1) * 16;
    int ncol0 = (warp & 1) * 128;
    size_t n0 = (size_t)blockIdx.x * 64;

    if (tid < CATD) s_ow[tid] = outw[tid];
    for (int i = tid; i < 2048; i += 256) {
        int o = i >> 8, jj = i & 255;
        s_fc2[o * 256 + jj] = fc2w[jj * 8 + o];
    }
    { int r = tid >> 2, q = tid & 3; rpart4[r][q] = 0.f; }

    float c[16][4];
    #pragma unroll
    for (int nt = 0; nt < 16; nt++)
        #pragma unroll
        for (int q = 0; q < 4; q++) c[nt][q] = 0.f;

    for (int kc = 0; kc < 4; kc++) {
        __syncthreads();
        #pragma unroll
        for (int q = 0; q < 4; q++) {
            int idx = q * 256 + tid;
            int r = idx >> 4, k4 = idx & 15;
            size_t row = n0 + r;
            float4 v = (row < NCELL)
                ? *(const float4*)(cat + row * CATD + kc * 64 + k4 * 4)
                : make_float4(0.f, 0.f, 0.f, 0.f);
            *(float4*)(As + r * AS_LD + k4 * 4) = v;
        }
        #pragma unroll
        for (int q = 0; q < 16; q++) {
            int idx = q * 256 + tid;
            int r = idx >> 6, j4 = idx & 63;
            float4 v = *(const float4*)(fc1w + (size_t)(kc * 64 + r) * 256 + j4 * 4);
            *(float4*)(Bs + r * BS_LD + j4 * 4) = v;
        }
        __syncthreads();
        {
            int r = tid >> 2, q = tid & 3;
            float a = 0.f;
            #pragma unroll
            for (int kk = 0; kk < 16; kk++)
                a += As[r * AS_LD + q * 16 + kk] * s_ow[kc * 64 + q * 16 + kk];
            rpart4[r][q] += a;
        }
        #pragma unroll
        for (int kk = 0; kk < 8; kk++) {
            int kb = kk * 8;
            uint32_t a0 = f2tf32(As[(mrow0 + gid) * AS_LD + kb + tig]);
            uint32_t a1 = f2tf32(As[(mrow0 + gid + 8) * AS_LD + kb + tig]);
            uint32_t a2 = f2tf32(As[(mrow0 + gid) * AS_LD + kb + tig + 4]);
            uint32_t a3 = f2tf32(As[(mrow0 + gid + 8) * AS_LD + kb + tig + 4]);
            #pragma unroll
            for (int nt = 0; nt < 16; nt++) {
                int col = ncol0 + nt * 8 + gid;
                uint32_t b0 = f2tf32(Bs[(kb + tig) * BS_LD + col]);
                uint32_t b1 = f2tf32(Bs[(kb + tig + 4) * BS_LD + col]);
                mma_tf32(c[nt], a0, a1, a2, a3, b0, b1);
            }
        }
    }
    __syncthreads();
    #pragma unroll
    for (int nt = 0; nt < 16; nt++) {
        int col0 = ncol0 + nt * 8 + 2 * tig;
        float bb0 = fc1b[col0], bb1 = fc1b[col0 + 1];
        Hs[(mrow0 + gid) * HS_LD + col0]     = fmaxf(c[nt][0] + bb0, 0.f);
        Hs[(mrow0 + gid) * HS_LD + col0 + 1] = fmaxf(c[nt][1] + bb1, 0.f);
        Hs[(mrow0 + gid + 8) * HS_LD + col0]     = fmaxf(c[nt][2] + bb0, 0.f);
        Hs[(mrow0 + gid + 8) * HS_LD + col0 + 1] = fmaxf(c[nt][3] + bb1, 0.f);
    }
    __syncthreads();
    #pragma unroll
    for (int pp = 0; pp < 2; pp++) {
        int p = tid + pp * 256;
        int r = p >> 3, o = p & 7;
        size_t row = n0 + r;
        float a = fc2b[o];
        const float4* h4 = (const float4*)(Hs + r * HS_LD);
        const float4* w4 = (const float4*)(s_fc2 + o * 256);
        #pragma unroll 8
        for (int jj = 0; jj < 64; jj++) {
            float4 h = h4[jj], w = w4[jj];
            a += h.x * w.x + h.y * w.y + h.z * w.z + h.w * w.w;
        }
        if (row < NCELL) nodes_out[row * OUTD + o] = fmaxf(a, 0.f);
    }
    if (tid < 64) {
        size_t row = n0 + tid;
        if (row < NCELL) {
            float s = outb[0] + rpart4[tid][0] + rpart4[tid][1] + rpart4[tid][2] + rpart4[tid][3];
            ret_out[row] = s;
        }
    }
}

// ---------------- launch ----------------
static inline int cdiv(long long a, long long b) { return (int)((a + b - 1) / b); }

extern "C" void kernel_launch(void* const* d_in, const int* in_sizes, int n_in,
                              void* d_out, int out_size) {
    const float* node_f     = (const float*)d_in[0];
    const float* net_f      = (const float*)d_in[1];
    const int*   sink_node  = (const int*)d_in[2];
    const int*   sink_net   = (const int*)d_in[3];
    const int*   src_node   = (const int*)d_in[4];
    const int*   src_net    = (const int*)d_in[5];
    const int*   batch      = (const int*)d_in[6];
    const float* w_node     = (const float*)d_in[8];
    const float* b_node     = (const float*)d_in[9];
    const float* w_net      = (const float*)d_in[10];
    const float* b_net      = (const float*)d_in[11];
    const float* vn_emb     = (const float*)d_in[12];
    const float* vn_mlp_w   = (const float*)d_in[13];
    const float* vn_mlp_b   = (const float*)d_in[14];
    const float* conv_net_w = (const float*)d_in[15];
    const float* conv_net_b = (const float*)d_in[16];
    const float* conv_node_w= (const float*)d_in[17];
    const float* conv_node_b= (const float*)d_in[18];
    const float* fc1_w      = (const float*)d_in[19];
    const float* fc1_b      = (const float*)d_in[20];
    const float* fc2_w      = (const float*)d_in[21];
    const float* fc2_b      = (const float*)d_in[22];
    const float* out_w      = (const float*)d_in[23];
    const float* out_b      = (const float*)d_in[24];

    static bool attr_done = false;
    if (!attr_done) {
        cudaFuncSetAttribute(k_head_mma, cudaFuncAttributeMaxDynamicSharedMemorySize, DSMEM_HEAD);
        cudaFuncSetAttribute(k_net_mma, cudaFuncAttributeMaxDynamicSharedMemorySize, DSMEM_CONV);
        cudaFuncSetAttribute(k_node_mma, cudaFuncAttributeMaxDynamicSharedMemorySize, DSMEM_CONV);
        attr_done = true;
    }

    int *p_cnt_n, *p_cnt_e, *p_cnt_comb, *p_off_net, *p_cur_net, *p_off_node, *p_cur_node;
    float *p_cat, *p_pool, *p_cntvn, *p_net;
    cudaGetSymbolAddress((void**)&p_cnt_n, g_cnt_n);
    cudaGetSymbolAddress((void**)&p_cnt_e, g_cnt_e);
    cudaGetSymbolAddress((void**)&p_cnt_comb, g_cnt_comb);
    cudaGetSymbolAddress((void**)&p_off_net, g_off_net);
    cudaGetSymbolAddress((void**)&p_cur_net, g_cur_net);
    cudaGetSymbolAddress((void**)&p_off_node, g_off_node);
    cudaGetSymbolAddress((void**)&p_cur_node, g_cur_node);
    cudaGetSymbolAddress((void**)&p_cat, g_cat);
    cudaGetSymbolAddress((void**)&p_pool, g_pool);
    cudaGetSymbolAddress((void**)&p_cntvn, g_cntvn);
    cudaGetSymbolAddress((void**)&p_net, g_net);

    // --- counts ---
    k_zeroi<<<cdiv(NCELL, 256), 256>>>(p_cnt_n, NCELL);
    k_zeroi<<<cdiv(MNET, 256), 256>>>(p_cnt_e, MNET);
    k_zeroi<<<cdiv(MNET, 256), 256>>>(p_cnt_comb, MNET);
    k_zerof<<<1, 64>>>(p_cntvn, VN);
    k_count_sink<<<cdiv(EKE, 256), 256>>>(sink_node, sink_net);
    k_count_src<<<cdiv(ESE, 256), 256>>>(src_net);
    k_addcnt<<<cdiv(MNET, 256), 256>>>();
    k_rsq_n<<<cdiv(NCELL, 256), 256>>>();
    k_rsq_e<<<cdiv(MNET, 256), 256>>>();
    k_cnt<<<128, 256>>>(batch);

    // --- CSR by net ---
    {
        int nb = cdiv(MNET, 1024);
        k_scan1<<<nb, 256>>>(p_cnt_comb, MNET);
        k_scan2<<<1, 1024>>>(nb);
        k_scan3<<<nb, 256>>>(p_cnt_comb, MNET, p_off_net, p_cur_net);
        k_sentinel<<<1, 1>>>(p_off_net, MNET, ECOMB);
    }
    // --- CSR by node ---
    {
        int nb = cdiv(NCELL, 1024);
        k_scan1<<<nb, 256>>>(p_cnt_n, NCELL);
        k_scan2<<<1, 1024>>>(nb);
        k_scan3<<<nb, 256>>>(p_cnt_n, NCELL, p_off_node, p_cur_node);
        k_sentinel<<<1, 1>>>(p_off_node, NCELL, EKE);
    }
    k_scat_net_src<<<cdiv(ESE, 256), 256>>>(src_node, src_net);
    k_scat_net_sink<<<cdiv(EKE, 256), 256>>>(sink_node, sink_net);
    k_scat_node<<<cdiv(EKE, 256), 256>>>(sink_node, sink_net);

    // --- embeddings ---
    k_embed<<<cdiv(NCELL, 16), 256>>>(node_f, w_node, b_node, p_cat, NCELL, CATD);
    k_embed<<<cdiv(MNET, 16), 256>>>(net_f, w_net, b_net, p_net, MNET, EMB);
    k_vninit<<<cdiv(VN * EMB, 256), 256>>>(vn_emb);

    // --- layers ---
    for (int l = 0; l < NL; l++) {
        int doPool = (l < NL - 1) ? 1 : 0;
        if (doPool) {
            k_zerof<<<cdiv(VN * EMB, 256), 256>>>(p_pool, VN * EMB);
            k_pool_cat<<<512, 256>>>(batch, l);
        }
        k_net_mma<<<cdiv(MNET, 64), 256, DSMEM_CONV>>>(conv_net_w + l * 4096, conv_net_b + l * 64, batch, l);
        k_node_mma<<<cdiv(NCELL, 64), 256, DSMEM_CONV>>>(conv_node_w + l * 4096, conv_node_b + l * 64, batch, l);
        if (doPool)
            k_vn<<<VN, EMB>>>(vn_mlp_w + l * 4096, vn_mlp_b + l * 64);
    }

    // --- head ---
    float* nodes_out = (float*)d_out;
    float* ret_out = (float*)d_out + (size_t)NCELL * OUTD;
    k_head_mma<<<cdiv(NCELL, 64), 256, DSMEM_HEAD>>>(fc1_w, fc1_b, fc2_w, fc2_b,
                                                     out_w, out_b, p_cat, nodes_out, ret_out);
}

// round 6
// speedup vs baseline: 1.9174x; 1.0070x over previous
#include <cuda_runtime.h>
#include <cstdint>

#define NCELL 500000
#define MNET  450000
#define EKE   2000000
#define ESE   500000
#define ECOMB (EKE + ESE)
#define EMB   64
#define VN    64
#define NL    3
#define CATD  256
#define OUTD  8

// ---------------- scratch ----------------
__device__ int   g_cnt_n[NCELL];
__device__ int   g_cnt_e[MNET];
__device__ int   g_cnt_comb[MNET];
__device__ int   g_off_net[MNET + 1];
__device__ int   g_cur_net[MNET];
__device__ int   g_off_node[NCELL + 1];
__device__ int   g_cur_node[NCELL];
__device__ int2  g_csr_net[ECOMB];
__device__ int2  g_csr_node[EKE];
__device__ int   g_partial[1024];
__device__ float g_rsq_n[NCELL];
__device__ float g_rsq_e[MNET];
__device__ float g_cat[(size_t)NCELL * CATD];
__device__ float g_net[(size_t)MNET * EMB];
__device__ float g_vn[VN * EMB];
__device__ float g_pool[VN * EMB];   // invariant: zero at kernel_launch entry
__device__ float g_cntvn[VN];

// ---------------- helpers ----------------
__device__ __forceinline__ uint32_t f2tf32(float v) {
    uint32_t r; asm("cvt.rna.tf32.f32 %0, %1;" : "=r"(r) : "f"(v)); return r;
}
__device__ __forceinline__ void split_tf32(float v, uint32_t& hi, uint32_t& lo) {
    hi = f2tf32(v);
    lo = f2tf32(v - __uint_as_float(hi));
}
__device__ __forceinline__ void mma_tf32(float* c, uint32_t a0, uint32_t a1, uint32_t a2,
                                         uint32_t a3, uint32_t b0, uint32_t b1) {
    asm("mma.sync.aligned.m16n8k8.row.col.f32.tf32.tf32.f32 "
        "{%0,%1,%2,%3},{%4,%5,%6,%7},{%8,%9},{%0,%1,%2,%3};"
        : "+f"(c[0]), "+f"(c[1]), "+f"(c[2]), "+f"(c[3])
        : "r"(a0), "r"(a1), "r"(a2), "r"(a3), "r"(b0), "r"(b1));
}

// ---------------- setup kernels ----------------
__global__ void k_zero_all() {
    int i = blockIdx.x * blockDim.x + threadIdx.x;
    if (i < NCELL) g_cnt_n[i] = 0;
    if (i < MNET) { g_cnt_e[i] = 0; g_cnt_comb[i] = 0; }
    if (i < VN) g_cntvn[i] = 0.f;
}
__global__ void k_count(const int* __restrict__ sn, const int* __restrict__ se,
                        const int* __restrict__ src_net) {
    int i = blockIdx.x * blockDim.x + threadIdx.x;
    if (i < EKE) { atomicAdd(&g_cnt_n[sn[i]], 1); atomicAdd(&g_cnt_e[se[i]], 1); }
    if (i < ESE) atomicAdd(&g_cnt_comb[src_net[i]], 1);
}
__global__ void k_addcnt_rsq() {
    int i = blockIdx.x * blockDim.x + threadIdx.x;
    if (i < MNET) {
        int ce = g_cnt_e[i];
        g_cnt_comb[i] += ce;
        g_rsq_e[i] = rsqrtf(fmaxf((float)ce, 1.f));
    }
    if (i < NCELL) g_rsq_n[i] = rsqrtf(fmaxf((float)g_cnt_n[i], 1.f));
}
__global__ void k_sentinel(int* a, int idx, int val) { a[idx] = val; }

// ---------------- 3-phase exclusive scan ----------------
__global__ void k_scan1(const int* __restrict__ cnt, int n) {
    __shared__ int s[256];
    int base = blockIdx.x * 1024, t = threadIdx.x;
    int sum = 0;
    #pragma unroll
    for (int q = 0; q < 4; q++) { int i = base + q * 256 + t; sum += (i < n) ? cnt[i] : 0; }
    s[t] = sum; __syncthreads();
    for (int st = 128; st > 0; st >>= 1) {
        if (t < st) s[t] += s[t + st];
        __syncthreads();
    }
    if (t == 0) g_partial[blockIdx.x] = s[0];
}
__global__ void k_scan2(int nb) {
    __shared__ int s[1024];
    int t = threadIdx.x;
    int v = (t < nb) ? g_partial[t] : 0;
    s[t] = v; __syncthreads();
    for (int st = 1; st < 1024; st <<= 1) {
        int a = (t >= st) ? s[t - st] : 0;
        __syncthreads();
        s[t] += a; __syncthreads();
    }
    if (t < nb) g_partial[t] = s[t] - v;
}
__global__ void k_scan3(const int* __restrict__ cnt, int n, int* __restrict__ off, int* __restrict__ cur) {
    __shared__ int s[256];
    int t = threadIdx.x, base = blockIdx.x * 1024;
    int v[4], sum = 0;
    #pragma unroll
    for (int q = 0; q < 4; q++) { int i = base + t * 4 + q; v[q] = (i < n) ? cnt[i] : 0; sum += v[q]; }
    s[t] = sum; __syncthreads();
    int mine = sum;
    for (int st = 1; st < 256; st <<= 1) {
        int a = (t >= st) ? s[t - st] : 0;
        __syncthreads();
        s[t] += a; __syncthreads();
    }
    int ex = s[t] - mine + g_partial[blockIdx.x];
    #pragma unroll
    for (int q = 0; q < 4; q++) {
        int i = base + t * 4 + q;
        if (i < n) { off[i] = ex; cur[i] = ex; ex += v[q]; }
    }
}

// ---------------- CSR scatters ----------------
__global__ void k_scat_net_src(const int* __restrict__ sn, const int* __restrict__ se) {
    int e = blockIdx.x * blockDim.x + threadIdx.x;
    if (e < ESE) {
        int pos = atomicAdd(&g_cur_net[se[e]], 1);
        g_csr_net[pos] = make_int2(sn[e], __float_as_int(1.f));
    }
}
__global__ void k_scat_sink(const int* __restrict__ sn, const int* __restrict__ se) {
    int e = blockIdx.x * blockDim.x + threadIdx.x;
    if (e < EKE) {
        int node = sn[e], net = se[e];
        float ew = g_rsq_n[node] * g_rsq_e[net];
        int pn = atomicAdd(&g_cur_net[net], 1);
        g_csr_net[pn] = make_int2(node, __float_as_int(ew));
        int pd = atomicAdd(&g_cur_node[node], 1);
        g_csr_node[pd] = make_int2(net, __float_as_int(ew));
    }
}

// ---------------- per-VN node counts ----------------
__global__ void k_cnt(const int* __restrict__ batch) {
    __shared__ float s[VN];
    int tid = threadIdx.x;
    if (tid < VN) s[tid] = 0.f;
    __syncthreads();
    for (int n = blockIdx.x * blockDim.x + tid; n < NCELL; n += gridDim.x * blockDim.x)
        atomicAdd(&s[batch[n]], 1.f);
    __syncthreads();
    if (tid < VN) atomicAdd(&g_cntvn[tid], s[tid]);
}
__global__ void k_vninit(const float* __restrict__ vn_emb) {
    int i = blockIdx.x * blockDim.x + threadIdx.x;
    if (i < VN * EMB) g_vn[i] = vn_emb[i & 63];
}

// ---------------- embedding ----------------
__global__ void k_embed(const float* __restrict__ feat,
                        const float* __restrict__ w, const float* __restrict__ b,
                        float* __restrict__ out, int nrows, int ostride) {
    __shared__ float s_w[16 * EMB];
    __shared__ float s_b[EMB];
    int tid = threadIdx.x;
    for (int i = tid; i < 16 * EMB; i += 256) s_w[i] = w[i];
    if (tid < EMB) s_b[tid] = b[tid];
    __syncthreads();
    int j = tid & 63, r = tid >> 6;
    int base = blockIdx.x * 16;
    for (int g = 0; g < 16; g += 4) {
        int row = base + g + r;
        if (row < nrows) {
            const float* f = feat + (size_t)row * 16;
            float acc = s_b[j];
            #pragma unroll
            for (int k = 0; k < 16; k++) acc += f[k] * s_w[k * EMB + j];
            out[(size_t)row * ostride + j] = fmaxf(acc, 0.f);
        }
    }
}

// ---------------- VN pooling from cat (pool = seg(cat_l, batch)) ----------------
__global__ void k_pool_cat(const int* __restrict__ batch, int l) {
    __shared__ float s[VN * EMB];
    int tid = threadIdx.x;
    for (int i = tid; i < VN * EMB; i += 256) s[i] = 0.f;
    __syncthreads();
    int j = tid & 63, r = tid >> 6;
    for (int n = blockIdx.x * 4 + r; n < NCELL; n += gridDim.x * 4) {
        int b = batch[n];
        atomicAdd(&s[b * EMB + j], g_cat[(size_t)n * CATD + l * EMB + j]);
    }
    __syncthreads();
    for (int i = tid; i < VN * EMB; i += 256) atomicAdd(&g_pool[i], s[i]);
}

// ---------------- VN update: vn += relu(((pool + cnt*vn)/max(cnt,1) + vn) @ W + b) ----------------
// also re-zeros g_pool (maintains entry invariant)
__global__ void k_vn(const float* __restrict__ w, const float* __restrict__ b) {
    int v = blockIdx.x, j = threadIdx.x;
    __shared__ float t[EMB];
    float cnt = g_cntvn[v];
    float vv = g_vn[v * EMB + j];
    t[j] = (g_pool[v * EMB + j] + cnt * vv) / fmaxf(cnt, 1.f) + vv;
    g_pool[v * EMB + j] = 0.f;
    __syncthreads();
    float acc = b[j];
    #pragma unroll
    for (int k = 0; k < EMB; k++) acc += t[k] * w[k * EMB + j];
    g_vn[v * EMB + j] = vv + fmaxf(acc, 0.f);
}

// =====================================================================
// Fused gather + 3xTF32 mma conv kernels (unroll-4 gather for MLP)
// =====================================================================
#define CLD 68
#define DSMEM_CONV ((64 * CLD + 64 * CLD + VN * EMB + EMB) * 4)

__device__ __forceinline__ void conv_mma_epilogue(
    float* As, float* Ws, const float* sb,
    int tid, long long row0, int nrows, float* __restrict__ outbuf,
    int ostride4, int ooff4)
{
    int warp = tid >> 5, lane = tid & 31;
    int gid = lane >> 2, tig = lane & 3;
    int mrow0 = (warp >> 1) * 16;
    int ncol0 = (warp & 1) * 32;

    float c[4][4];
    #pragma unroll
    for (int nt = 0; nt < 4; nt++)
        #pragma unroll
        for (int q = 0; q < 4; q++) c[nt][q] = 0.f;

    #pragma unroll
    for (int kk = 0; kk < 8; kk++) {
        int kb = kk * 8;
        uint32_t ah0, al0, ah1, al1, ah2, al2, ah3, al3;
        split_tf32(As[(mrow0 + gid) * CLD + kb + tig], ah0, al0);
        split_tf32(As[(mrow0 + gid + 8) * CLD + kb + tig], ah1, al1);
        split_tf32(As[(mrow0 + gid) * CLD + kb + tig + 4], ah2, al2);
        split_tf32(As[(mrow0 + gid + 8) * CLD + kb + tig + 4], ah3, al3);
        #pragma unroll
        for (int nt = 0; nt < 4; nt++) {
            int col = ncol0 + nt * 8 + gid;
            uint32_t bh0, bl0, bh1, bl1;
            split_tf32(Ws[(kb + tig) * CLD + col], bh0, bl0);
            split_tf32(Ws[(kb + tig + 4) * CLD + col], bh1, bl1);
            mma_tf32(c[nt], ah0, ah1, ah2, ah3, bh0, bh1);
            mma_tf32(c[nt], ah0, ah1, ah2, ah3, bl0, bl1);
            mma_tf32(c[nt], al0, al1, al2, al3, bh0, bh1);
        }
    }
    __syncthreads();
    #pragma unroll
    for (int nt = 0; nt < 4; nt++) {
        int col0 = ncol0 + nt * 8 + 2 * tig;
        float b0 = sb[col0], b1 = sb[col0 + 1];
        As[(mrow0 + gid) * CLD + col0]     = fmaxf(c[nt][0] + b0, 0.f);
        As[(mrow0 + gid) * CLD + col0 + 1] = fmaxf(c[nt][1] + b1, 0.f);
        As[(mrow0 + gid + 8) * CLD + col0]     = fmaxf(c[nt][2] + b0, 0.f);
        As[(mrow0 + gid + 8) * CLD + col0 + 1] = fmaxf(c[nt][3] + b1, 0.f);
    }
    __syncthreads();
    #pragma unroll
    for (int q = 0; q < 4; q++) {
        int idx = q * 256 + tid;
        int r = idx >> 4, c4 = idx & 15;
        long long row = row0 + r;
        if (row < nrows) {
            float4 v = *(const float4*)(As + r * CLD + c4 * 4);
            ((float4*)outbuf)[row * ostride4 + ooff4 + c4] = v;
        }
    }
}

__global__ __launch_bounds__(256) void k_net_mma(
    const float* __restrict__ W, const float* __restrict__ b,
    const int* __restrict__ batch, int l) {
    extern __shared__ float sm[];
    float* As = sm;
    float* Ws = sm + 64 * CLD;
    float* vns = sm + 128 * CLD;
    float* sb = vns + VN * EMB;
    int tid = threadIdx.x;
    for (int i = tid; i < EMB * EMB; i += 256) Ws[(i >> 6) * CLD + (i & 63)] = W[i];
    for (int i = tid; i < VN * EMB; i += 256) vns[i] = g_vn[i];
    if (tid < EMB) sb[tid] = b[tid];
    __syncthreads();

    int warp = tid >> 5, lane = tid & 31;
    long long row0 = (long long)blockIdx.x * 64;
    const float2* cat2 = (const float2*)g_cat;
    const float2* net2 = (const float2*)g_net;
    const float2* vn2 = (const float2*)vns;

    for (int q = 0; q < 8; q++) {
        int r = warp * 8 + q;
        long long netid = row0 + r;
        float2 acc = make_float2(0.f, 0.f);
        if (netid < MNET) {
            acc = net2[netid * 32 + lane];
            int p0 = g_off_net[netid], p1 = g_off_net[netid + 1];
            int p = p0;
            for (; p + 3 < p1; p += 4) {
                int2 e0 = g_csr_net[p], e1 = g_csr_net[p + 1];
                int2 e2 = g_csr_net[p + 2], e3 = g_csr_net[p + 3];
                int b0 = batch[e0.x], b1 = batch[e1.x], b2 = batch[e2.x], b3 = batch[e3.x];
                float2 v0 = cat2[(size_t)e0.x * 128 + l * 32 + lane];
                float2 v1 = cat2[(size_t)e1.x * 128 + l * 32 + lane];
                float2 v2 = cat2[(size_t)e2.x * 128 + l * 32 + lane];
                float2 v3 = cat2[(size_t)e3.x * 128 + l * 32 + lane];
                float2 u0 = vn2[b0 * 32 + lane];
                float2 u1 = vn2[b1 * 32 + lane];
                float2 u2 = vn2[b2 * 32 + lane];
                float2 u3 = vn2[b3 * 32 + lane];
                float w0 = __int_as_float(e0.y), w1 = __int_as_float(e1.y);
                float w2 = __int_as_float(e2.y), w3 = __int_as_float(e3.y);
                acc.x += w0 * (v0.x + u0.x) + w1 * (v1.x + u1.x)
                       + w2 * (v2.x + u2.x) + w3 * (v3.x + u3.x);
                acc.y += w0 * (v0.y + u0.y) + w1 * (v1.y + u1.y)
                       + w2 * (v2.y + u2.y) + w3 * (v3.y + u3.y);
            }
            for (; p < p1; p++) {
                int2 e0 = g_csr_net[p];
                int b0 = batch[e0.x];
                float2 v0 = cat2[(size_t)e0.x * 128 + l * 32 + lane];
                float2 u0 = vn2[b0 * 32 + lane];
                float w0 = __int_as_float(e0.y);
                acc.x += w0 * (v0.x + u0.x);
                acc.y += w0 * (v0.y + u0.y);
            }
        }
        *(float2*)(As + r * CLD + 2 * lane) = acc;
    }
    __syncthreads();
    conv_mma_epilogue(As, Ws, sb, tid, row0, MNET, (float*)g_net, 16, 0);
}

__global__ __launch_bounds__(256) void k_node_mma(
    const float* __restrict__ W, const float* __restrict__ b,
    const int* __restrict__ batch, int l) {
    extern __shared__ float sm[];
    float* As = sm;
    float* Ws = sm + 64 * CLD;
    float* vns = sm + 128 * CLD;
    float* sb = vns + VN * EMB;
    int tid = threadIdx.x;
    for (int i = tid; i < EMB * EMB; i += 256) Ws[(i >> 6) * CLD + (i & 63)] = W[i];
    for (int i = tid; i < VN * EMB; i += 256) vns[i] = g_vn[i];
    if (tid < EMB) sb[tid] = b[tid];
    __syncthreads();

    int warp = tid >> 5, lane = tid & 31;
    long long row0 = (long long)blockIdx.x * 64;
    const float2* cat2 = (const float2*)g_cat;
    const float2* net2 = (const float2*)g_net;
    const float2* vn2 = (const float2*)vns;

    for (int q = 0; q < 8; q++) {
        int r = warp * 8 + q;
        long long node = row0 + r;
        float2 acc = make_float2(0.f, 0.f);
        if (node < NCELL) {
            int bb = batch[node];
            float2 v = cat2[node * 128 + l * 32 + lane];
            float2 u = vn2[bb * 32 + lane];
            acc.x = v.x + u.x; acc.y = v.y + u.y;
            int p0 = g_off_node[node], p1 = g_off_node[node + 1];
            int p = p0;
            for (; p + 3 < p1; p += 4) {
                int2 e0 = g_csr_node[p], e1 = g_csr_node[p + 1];
                int2 e2 = g_csr_node[p + 2], e3 = g_csr_node[p + 3];
                float2 v0 = net2[(size_t)e0.x * 32 + lane];
                float2 v1 = net2[(size_t)e1.x * 32 + lane];
                float2 v2 = net2[(size_t)e2.x * 32 + lane];
                float2 v3 = net2[(size_t)e3.x * 32 + lane];
                float w0 = __int_as_float(e0.y), w1 = __int_as_float(e1.y);
                float w2 = __int_as_float(e2.y), w3 = __int_as_float(e3.y);
                acc.x += w0 * v0.x + w1 * v1.x + w2 * v2.x + w3 * v3.x;
                acc.y += w0 * v0.y + w1 * v1.y + w2 * v2.y + w3 * v3.y;
            }
            for (; p < p1; p++) {
                int2 e0 = g_csr_node[p];
                float2 v0 = net2[(size_t)e0.x * 32 + lane];
                float w0 = __int_as_float(e0.y);
                acc.x += w0 * v0.x; acc.y += w0 * v0.y;
            }
        }
        *(float2*)(As + r * CLD + 2 * lane) = acc;
    }
    __syncthreads();
    conv_mma_epilogue(As, Ws, sb, tid, row0, NCELL, (float*)g_cat, 64, (l + 1) * 16);
}

// ---------------- head (tf32 mma for fc1) ----------------
#define AS_LD 68
#define BS_LD 260
#define HS_LD 264
#define DSMEM_HEAD ((64 * AS_LD + 64 * BS_LD) * 4)

__global__ __launch_bounds__(256) void k_head_mma(
    const float* __restrict__ fc1w, const float* __restrict__ fc1b,
    const float* __restrict__ fc2w, const float* __restrict__ fc2b,
    const float* __restrict__ outw, const float* __restrict__ outb,
    const float* __restrict__ cat,
    float* __restrict__ nodes_out, float* __restrict__ ret_out) {
    extern __shared__ float sm[];
    float* As = sm;
    float* Bs = sm + 64 * AS_LD;
    float* Hs = sm;
    __shared__ float s_ow[CATD];
    __shared__ float s_fc2[8 * 256];
    __shared__ float rpart4[64][4];

    int tid = threadIdx.x;
    int warp = tid >> 5, lane = tid & 31;
    int gid = lane >> 2, tig = lane & 3;
    int mrow0 = (warp >> 1) * 16;
    int ncol0 = (warp & 1) * 128;
    size_t n0 = (size_t)blockIdx.x * 64;

    if (tid < CATD) s_ow[tid] = outw[tid];
    for (int i = tid; i < 2048; i += 256) {
        int o = i >> 8, jj = i & 255;
        s_fc2[o * 256 + jj] = fc2w[jj * 8 + o];
    }
    { int r = tid >> 2, q = tid & 3; rpart4[r][q] = 0.f; }

    float c[16][4];
    #pragma unroll
    for (int nt = 0; nt < 16; nt++)
        #pragma unroll
        for (int q = 0; q < 4; q++) c[nt][q] = 0.f;

    for (int kc = 0; kc < 4; kc++) {
        __syncthreads();
        #pragma unroll
        for (int q = 0; q < 4; q++) {
            int idx = q * 256 + tid;
            int r = idx >> 4, k4 = idx & 15;
            size_t row = n0 + r;
            float4 v = (row < NCELL)
                ? *(const float4*)(cat + row * CATD + kc * 64 + k4 * 4)
                : make_float4(0.f, 0.f, 0.f, 0.f);
            *(float4*)(As + r * AS_LD + k4 * 4) = v;
        }
        #pragma unroll
        for (int q = 0; q < 16; q++) {
            int idx = q * 256 + tid;
            int r = idx >> 6, j4 = idx & 63;
            float4 v = *(const float4*)(fc1w + (size_t)(kc * 64 + r) * 256 + j4 * 4);
            *(float4*)(Bs + r * BS_LD + j4 * 4) = v;
        }
        __syncthreads();
        {
            int r = tid >> 2, q = tid & 3;
            float a = 0.f;
            #pragma unroll
            for (int kk = 0; kk < 16; kk++)
                a += As[r * AS_LD + q * 16 + kk] * s_ow[kc * 64 + q * 16 + kk];
            rpart4[r][q] += a;
        }
        #pragma unroll
        for (int kk = 0; kk < 8; kk++) {
            int kb = kk * 8;
            uint32_t a0 = f2tf32(As[(mrow0 + gid) * AS_LD + kb + tig]);
            uint32_t a1 = f2tf32(As[(mrow0 + gid + 8) * AS_LD + kb + tig]);
            uint32_t a2 = f2tf32(As[(mrow0 + gid) * AS_LD + kb + tig + 4]);
            uint32_t a3 = f2tf32(As[(mrow0 + gid + 8) * AS_LD + kb + tig + 4]);
            #pragma unroll
            for (int nt = 0; nt < 16; nt++) {
                int col = ncol0 + nt * 8 + gid;
                uint32_t b0 = f2tf32(Bs[(kb + tig) * BS_LD + col]);
                uint32_t b1 = f2tf32(Bs[(kb + tig + 4) * BS_LD + col]);
                mma_tf32(c[nt], a0, a1, a2, a3, b0, b1);
            }
        }
    }
    __syncthreads();
    #pragma unroll
    for (int nt = 0; nt < 16; nt++) {
        int col0 = ncol0 + nt * 8 + 2 * tig;
        float bb0 = fc1b[col0], bb1 = fc1b[col0 + 1];
        Hs[(mrow0 + gid) * HS_LD + col0]     = fmaxf(c[nt][0] + bb0, 0.f);
        Hs[(mrow0 + gid) * HS_LD + col0 + 1] = fmaxf(c[nt][1] + bb1, 0.f);
        Hs[(mrow0 + gid + 8) * HS_LD + col0]     = fmaxf(c[nt][2] + bb0, 0.f);
        Hs[(mrow0 + gid + 8) * HS_LD + col0 + 1] = fmaxf(c[nt][3] + bb1, 0.f);
    }
    __syncthreads();
    #pragma unroll
    for (int pp = 0; pp < 2; pp++) {
        int p = tid + pp * 256;
        int r = p >> 3, o = p & 7;
        size_t row = n0 + r;
        float a = fc2b[o];
        const float4* h4 = (const float4*)(Hs + r * HS_LD);
        const float4* w4 = (const float4*)(s_fc2 + o * 256);
        #pragma unroll 8
        for (int jj = 0; jj < 64; jj++) {
            float4 h = h4[jj], w = w4[jj];
            a += h.x * w.x + h.y * w.y + h.z * w.z + h.w * w.w;
        }
        if (row < NCELL) nodes_out[row * OUTD + o] = fmaxf(a, 0.f);
    }
    if (tid < 64) {
        size_t row = n0 + tid;
        if (row < NCELL) {
            float s = outb[0] + rpart4[tid][0] + rpart4[tid][1] + rpart4[tid][2] + rpart4[tid][3];
            ret_out[row] = s;
        }
    }
}

// ---------------- launch ----------------
static inline int cdiv(long long a, long long b) { return (int)((a + b - 1) / b); }

extern "C" void kernel_launch(void* const* d_in, const int* in_sizes, int n_in,
                              void* d_out, int out_size) {
    const float* node_f     = (const float*)d_in[0];
    const float* net_f      = (const float*)d_in[1];
    const int*   sink_node  = (const int*)d_in[2];
    const int*   sink_net   = (const int*)d_in[3];
    const int*   src_node   = (const int*)d_in[4];
    const int*   src_net    = (const int*)d_in[5];
    const int*   batch      = (const int*)d_in[6];
    const float* w_node     = (const float*)d_in[8];
    const float* b_node     = (const float*)d_in[9];
    const float* w_net      = (const float*)d_in[10];
    const float* b_net      = (const float*)d_in[11];
    const float* vn_emb     = (const float*)d_in[12];
    const float* vn_mlp_w   = (const float*)d_in[13];
    const float* vn_mlp_b   = (const float*)d_in[14];
    const float* conv_net_w = (const float*)d_in[15];
    const float* conv_net_b = (const float*)d_in[16];
    const float* conv_node_w= (const float*)d_in[17];
    const float* conv_node_b= (const float*)d_in[18];
    const float* fc1_w      = (const float*)d_in[19];
    const float* fc1_b      = (const float*)d_in[20];
    const float* fc2_w      = (const float*)d_in[21];
    const float* fc2_b      = (const float*)d_in[22];
    const float* out_w      = (const float*)d_in[23];
    const float* out_b      = (const float*)d_in[24];

    static bool attr_done = false;
    if (!attr_done) {
        cudaFuncSetAttribute(k_head_mma, cudaFuncAttributeMaxDynamicSharedMemorySize, DSMEM_HEAD);
        cudaFuncSetAttribute(k_net_mma, cudaFuncAttributeMaxDynamicSharedMemorySize, DSMEM_CONV);
        cudaFuncSetAttribute(k_node_mma, cudaFuncAttributeMaxDynamicSharedMemorySize, DSMEM_CONV);
        attr_done = true;
    }

    int *p_cnt_n, *p_cnt_comb, *p_off_net, *p_cur_net, *p_off_node, *p_cur_node;
    float *p_cat, *p_net;
    cudaGetSymbolAddress((void**)&p_cnt_n, g_cnt_n);
    cudaGetSymbolAddress((void**)&p_cnt_comb, g_cnt_comb);
    cudaGetSymbolAddress((void**)&p_off_net, g_off_net);
    cudaGetSymbolAddress((void**)&p_cur_net, g_cur_net);
    cudaGetSymbolAddress((void**)&p_off_node, g_off_node);
    cudaGetSymbolAddress((void**)&p_cur_node, g_cur_node);
    cudaGetSymbolAddress((void**)&p_cat, g_cat);
    cudaGetSymbolAddress((void**)&p_net, g_net);

    // --- counts / weights ---
    k_zero_all<<<cdiv(NCELL, 256), 256>>>();
    k_count<<<cdiv(EKE, 256), 256>>>(sink_node, sink_net, src_net);
    k_addcnt_rsq<<<cdiv(NCELL, 256), 256>>>();
    k_cnt<<<128, 256>>>(batch);

    // --- CSR by net ---
    {
        int nb = cdiv(MNET, 1024);
        k_scan1<<<nb, 256>>>(p_cnt_comb, MNET);
        k_scan2<<<1, 1024>>>(nb);
        k_scan3<<<nb, 256>>>(p_cnt_comb, MNET, p_off_net, p_cur_net);
        k_sentinel<<<1, 1>>>(p_off_net, MNET, ECOMB);
    }
    // --- CSR by node ---
    {
        int nb = cdiv(NCELL, 1024);
        k_scan1<<<nb, 256>>>(p_cnt_n, NCELL);
        k_scan2<<<1, 1024>>>(nb);
        k_scan3<<<nb, 256>>>(p_cnt_n, NCELL, p_off_node, p_cur_node);
        k_sentinel<<<1, 1>>>(p_off_node, NCELL, EKE);
    }
    k_scat_net_src<<<cdiv(ESE, 256), 256>>>(src_node, src_net);
    k_scat_sink<<<cdiv(EKE, 256), 256>>>(sink_node, sink_net);

    // --- embeddings ---
    k_embed<<<cdiv(NCELL, 16), 256>>>(node_f, w_node, b_node, p_cat, NCELL, CATD);
    k_embed<<<cdiv(MNET, 16), 256>>>(net_f, w_net, b_net, p_net, MNET, EMB);
    k_vninit<<<cdiv(VN * EMB, 256), 256>>>(vn_emb);

    // --- layers ---
    for (int l = 0; l < NL; l++) {
        int doPool = (l < NL - 1) ? 1 : 0;
        if (doPool) k_pool_cat<<<512, 256>>>(batch, l);
        k_net_mma<<<cdiv(MNET, 64), 256, DSMEM_CONV>>>(conv_net_w + l * 4096, conv_net_b + l * 64, batch, l);
        k_node_mma<<<cdiv(NCELL, 64), 256, DSMEM_CONV>>>(conv_node_w + l * 4096, conv_node_b + l * 64, batch, l);
        if (doPool)
            k_vn<<<VN, EMB>>>(vn_mlp_w + l * 4096, vn_mlp_b + l * 64);
    }

    // --- head ---
    float* nodes_out = (float*)d_out;
    float* ret_out = (float*)d_out + (size_t)NCELL * OUTD;
    k_head_mma<<<cdiv(NCELL, 64), 256, DSMEM_HEAD>>>(fc1_w, fc1_b, fc2_w, fc2_b,
                                                     out_w, out_b, p_cat, nodes_out, ret_out);
}

// round 7
// speedup vs baseline: 2.2635x; 1.1805x over previous
#include <cuda_runtime.h>
#include <cstdint>

#define NCELL 500000
#define MNET  450000
#define EKE   2000000
#define ESE   500000
#define ECOMB (EKE + ESE)
#define EMB   64
#define VN    64
#define NL    3
#define CATD  256
#define OUTD  8
#define NODE_MASK 0x7FFFF

// ---------------- scratch ----------------
__device__ int   g_cnt_n[NCELL];
__device__ int   g_cnt_e[MNET];
__device__ int   g_cnt_comb[MNET];
__device__ int   g_off_net[MNET + 1];
__device__ int   g_cur_net[MNET];
__device__ int   g_off_node[NCELL + 1];
__device__ int   g_cur_node[NCELL];
__device__ int2  g_csr_net[ECOMB];     // (packed node|b<<19, weight bits)
__device__ int2  g_csr_node[EKE];      // (net, weight bits)
__device__ int   g_partial[1024];
__device__ float g_rsq_n[NCELL];
__device__ float g_rsq_e[MNET];
__device__ float g_cat[(size_t)NCELL * CATD];
__device__ float g_net[(size_t)MNET * EMB];
__device__ float g_vn[VN * EMB];
__device__ float g_pool[VN * EMB];   // invariant: zero at kernel_launch entry
__device__ float g_cntvn[VN];

// ---------------- helpers ----------------
__device__ __forceinline__ uint32_t f2tf32(float v) {
    uint32_t r; asm("cvt.rna.tf32.f32 %0, %1;" : "=r"(r) : "f"(v)); return r;
}
__device__ __forceinline__ void split_tf32(float v, uint32_t& hi, uint32_t& lo) {
    hi = f2tf32(v);
    lo = f2tf32(v - __uint_as_float(hi));
}
__device__ __forceinline__ void mma_tf32(float* c, uint32_t a0, uint32_t a1, uint32_t a2,
                                         uint32_t a3, uint32_t b0, uint32_t b1) {
    asm("mma.sync.aligned.m16n8k8.row.col.f32.tf32.tf32.f32 "
        "{%0,%1,%2,%3},{%4,%5,%6,%7},{%8,%9},{%0,%1,%2,%3};"
        : "+f"(c[0]), "+f"(c[1]), "+f"(c[2]), "+f"(c[3])
        : "r"(a0), "r"(a1), "r"(a2), "r"(a3), "r"(b0), "r"(b1));
}

// ---------------- setup kernels ----------------
__global__ void k_zero_all() {
    int i = blockIdx.x * blockDim.x + threadIdx.x;
    if (i < NCELL) g_cnt_n[i] = 0;
    if (i < MNET) { g_cnt_e[i] = 0; g_cnt_comb[i] = 0; }
    if (i < VN) g_cntvn[i] = 0.f;
}
__global__ void k_count(const int* __restrict__ sn, const int* __restrict__ se,
                        const int* __restrict__ src_net) {
    int i = blockIdx.x * blockDim.x + threadIdx.x;
    if (i < EKE) { atomicAdd(&g_cnt_n[sn[i]], 1); atomicAdd(&g_cnt_e[se[i]], 1); }
    if (i < ESE) atomicAdd(&g_cnt_comb[src_net[i]], 1);
}
__global__ void k_addcnt_rsq() {
    int i = blockIdx.x * blockDim.x + threadIdx.x;
    if (i < MNET) {
        int ce = g_cnt_e[i];
        g_cnt_comb[i] += ce;
        g_rsq_e[i] = rsqrtf(fmaxf((float)ce, 1.f));
    }
    if (i < NCELL) g_rsq_n[i] = rsqrtf(fmaxf((float)g_cnt_n[i], 1.f));
}
__global__ void k_sentinel(int* a, int idx, int val) { a[idx] = val; }

// ---------------- 3-phase exclusive scan ----------------
__global__ void k_scan1(const int* __restrict__ cnt, int n) {
    __shared__ int s[256];
    int base = blockIdx.x * 1024, t = threadIdx.x;
    int sum = 0;
    #pragma unroll
    for (int q = 0; q < 4; q++) { int i = base + q * 256 + t; sum += (i < n) ? cnt[i] : 0; }
    s[t] = sum; __syncthreads();
    for (int st = 128; st > 0; st >>= 1) {
        if (t < st) s[t] += s[t + st];
        __syncthreads();
    }
    if (t == 0) g_partial[blockIdx.x] = s[0];
}
__global__ void k_scan2(int nb) {
    __shared__ int s[1024];
    int t = threadIdx.x;
    int v = (t < nb) ? g_partial[t] : 0;
    s[t] = v; __syncthreads();
    for (int st = 1; st < 1024; st <<= 1) {
        int a = (t >= st) ? s[t - st] : 0;
        __syncthreads();
        s[t] += a; __syncthreads();
    }
    if (t < nb) g_partial[t] = s[t] - v;
}
__global__ void k_scan3(const int* __restrict__ cnt, int n, int* __restrict__ off, int* __restrict__ cur) {
    __shared__ int s[256];
    int t = threadIdx.x, base = blockIdx.x * 1024;
    int v[4], sum = 0;
    #pragma unroll
    for (int q = 0; q < 4; q++) { int i = base + t * 4 + q; v[q] = (i < n) ? cnt[i] : 0; sum += v[q]; }
    s[t] = sum; __syncthreads();
    int mine = sum;
    for (int st = 1; st < 256; st <<= 1) {
        int a = (t >= st) ? s[t - st] : 0;
        __syncthreads();
        s[t] += a; __syncthreads();
    }
    int ex = s[t] - mine + g_partial[blockIdx.x];
    #pragma unroll
    for (int q = 0; q < 4; q++) {
        int i = base + t * 4 + q;
        if (i < n) { off[i] = ex; cur[i] = ex; ex += v[q]; }
    }
}

// ---------------- CSR scatters (batch packed into node id for net-CSR) ----------------
__global__ void k_scat_net_src(const int* __restrict__ sn, const int* __restrict__ se,
                               const int* __restrict__ batch) {
    int e = blockIdx.x * blockDim.x + threadIdx.x;
    if (e < ESE) {
        int node = sn[e];
        int packed = node | (batch[node] << 19);
        int pos = atomicAdd(&g_cur_net[se[e]], 1);
        g_csr_net[pos] = make_int2(packed, __float_as_int(1.f));
    }
}
__global__ void k_scat_sink(const int* __restrict__ sn, const int* __restrict__ se,
                            const int* __restrict__ batch) {
    int e = blockIdx.x * blockDim.x + threadIdx.x;
    if (e < EKE) {
        int node = sn[e], net = se[e];
        float ew = g_rsq_n[node] * g_rsq_e[net];
        int packed = node | (batch[node] << 19);
        int pn = atomicAdd(&g_cur_net[net], 1);
        g_csr_net[pn] = make_int2(packed, __float_as_int(ew));
        int pd = atomicAdd(&g_cur_node[node], 1);
        g_csr_node[pd] = make_int2(net, __float_as_int(ew));
    }
}

// ---------------- per-VN node counts ----------------
__global__ void k_cnt(const int* __restrict__ batch) {
    __shared__ float s[VN];
    int tid = threadIdx.x;
    if (tid < VN) s[tid] = 0.f;
    __syncthreads();
    for (int n = blockIdx.x * blockDim.x + tid; n < NCELL; n += gridDim.x * blockDim.x)
        atomicAdd(&s[batch[n]], 1.f);
    __syncthreads();
    if (tid < VN) atomicAdd(&g_cntvn[tid], s[tid]);
}
__global__ void k_vninit(const float* __restrict__ vn_emb) {
    int i = blockIdx.x * blockDim.x + threadIdx.x;
    if (i < VN * EMB) g_vn[i] = vn_emb[i & 63];
}

// ---------------- embedding ----------------
__global__ void k_embed(const float* __restrict__ feat,
                        const float* __restrict__ w, const float* __restrict__ b,
                        float* __restrict__ out, int nrows, int ostride) {
    __shared__ float s_w[16 * EMB];
    __shared__ float s_b[EMB];
    int tid = threadIdx.x;
    for (int i = tid; i < 16 * EMB; i += 256) s_w[i] = w[i];
    if (tid < EMB) s_b[tid] = b[tid];
    __syncthreads();
    int j = tid & 63, r = tid >> 6;
    int base = blockIdx.x * 16;
    for (int g = 0; g < 16; g += 4) {
        int row = base + g + r;
        if (row < nrows) {
            const float* f = feat + (size_t)row * 16;
            float acc = s_b[j];
            #pragma unroll
            for (int k = 0; k < 16; k++) acc += f[k] * s_w[k * EMB + j];
            out[(size_t)row * ostride + j] = fmaxf(acc, 0.f);
        }
    }
}

// ---------------- VN pooling from cat (pool = seg(cat_l, batch)), float4 ----------------
__global__ void k_pool_cat(const int* __restrict__ batch, int l) {
    __shared__ float s[VN * EMB];
    int tid = threadIdx.x;
    for (int i = tid; i < VN * EMB; i += 256) s[i] = 0.f;
    __syncthreads();
    int c0 = (tid & 15) * 4, r = tid >> 4;   // 16 rows x 16 col-groups
    for (long long n = (long long)blockIdx.x * 16 + r; n < NCELL; n += (long long)gridDim.x * 16) {
        int b = batch[n];
        float4 v = *(const float4*)&g_cat[n * CATD + l * EMB + c0];
        atomicAdd(&s[b * EMB + c0 + 0], v.x);
        atomicAdd(&s[b * EMB + c0 + 1], v.y);
        atomicAdd(&s[b * EMB + c0 + 2], v.z);
        atomicAdd(&s[b * EMB + c0 + 3], v.w);
    }
    __syncthreads();
    for (int i = tid; i < VN * EMB; i += 256) atomicAdd(&g_pool[i], s[i]);
}

// ---------------- VN update (re-zeros g_pool) ----------------
__global__ void k_vn(const float* __restrict__ w, const float* __restrict__ b) {
    int v = blockIdx.x, j = threadIdx.x;
    __shared__ float t[EMB];
    float cnt = g_cntvn[v];
    float vv = g_vn[v * EMB + j];
    t[j] = (g_pool[v * EMB + j] + cnt * vv) / fmaxf(cnt, 1.f) + vv;
    g_pool[v * EMB + j] = 0.f;
    __syncthreads();
    float acc = b[j];
    #pragma unroll
    for (int k = 0; k < EMB; k++) acc += t[k] * w[k * EMB + j];
    g_vn[v * EMB + j] = vv + fmaxf(acc, 0.f);
}

// =====================================================================
// Persistent fused gather + 3xTF32 mma conv kernels
// =====================================================================
#define CLD 68
#define DSMEM_CONV ((64 * CLD + 64 * CLD + VN * EMB + EMB) * 4)
#define CONV_GRID 592
#define NTILES_NET  ((MNET + 63) / 64)
#define NTILES_NODE ((NCELL + 63) / 64)

__device__ __forceinline__ void conv_mma_epilogue(
    float* As, float* Ws, const float* sb,
    int tid, long long row0, int nrows, float* __restrict__ outbuf,
    int ostride4, int ooff4)
{
    int warp = tid >> 5, lane = tid & 31;
    int gid = lane >> 2, tig = lane & 3;
    int mrow0 = (warp >> 1) * 16;
    int ncol0 = (warp & 1) * 32;

    float c[4][4];
    #pragma unroll
    for (int nt = 0; nt < 4; nt++)
        #pragma unroll
        for (int q = 0; q < 4; q++) c[nt][q] = 0.f;

    #pragma unroll
    for (int kk = 0; kk < 8; kk++) {
        int kb = kk * 8;
        uint32_t ah0, al0, ah1, al1, ah2, al2, ah3, al3;
        split_tf32(As[(mrow0 + gid) * CLD + kb + tig], ah0, al0);
        split_tf32(As[(mrow0 + gid + 8) * CLD + kb + tig], ah1, al1);
        split_tf32(As[(mrow0 + gid) * CLD + kb + tig + 4], ah2, al2);
        split_tf32(As[(mrow0 + gid + 8) * CLD + kb + tig + 4], ah3, al3);
        #pragma unroll
        for (int nt = 0; nt < 4; nt++) {
            int col = ncol0 + nt * 8 + gid;
            uint32_t bh0, bl0, bh1, bl1;
            split_tf32(Ws[(kb + tig) * CLD + col], bh0, bl0);
            split_tf32(Ws[(kb + tig + 4) * CLD + col], bh1, bl1);
            mma_tf32(c[nt], ah0, ah1, ah2, ah3, bh0, bh1);
            mma_tf32(c[nt], ah0, ah1, ah2, ah3, bl0, bl1);
            mma_tf32(c[nt], al0, al1, al2, al3, bh0, bh1);
        }
    }
    __syncthreads();
    #pragma unroll
    for (int nt = 0; nt < 4; nt++) {
        int col0 = ncol0 + nt * 8 + 2 * tig;
        float b0 = sb[col0], b1 = sb[col0 + 1];
        As[(mrow0 + gid) * CLD + col0]     = fmaxf(c[nt][0] + b0, 0.f);
        As[(mrow0 + gid) * CLD + col0 + 1] = fmaxf(c[nt][1] + b1, 0.f);
        As[(mrow0 + gid + 8) * CLD + col0]     = fmaxf(c[nt][2] + b0, 0.f);
        As[(mrow0 + gid + 8) * CLD + col0 + 1] = fmaxf(c[nt][3] + b1, 0.f);
    }
    __syncthreads();
    #pragma unroll
    for (int q = 0; q < 4; q++) {
        int idx = q * 256 + tid;
        int r = idx >> 4, c4 = idx & 15;
        long long row = row0 + r;
        if (row < nrows) {
            float4 v = *(const float4*)(As + r * CLD + c4 * 4);
            ((float4*)outbuf)[row * ostride4 + ooff4 + c4] = v;
        }
    }
}

__global__ __launch_bounds__(256) void k_net_mma(
    const float* __restrict__ W, const float* __restrict__ b, int l) {
    extern __shared__ float sm[];
    float* As = sm;
    float* Ws = sm + 64 * CLD;
    float* vns = sm + 128 * CLD;
    float* sb = vns + VN * EMB;
    int tid = threadIdx.x;
    for (int i = tid; i < EMB * EMB; i += 256) Ws[(i >> 6) * CLD + (i & 63)] = W[i];
    for (int i = tid; i < VN * EMB; i += 256) vns[i] = g_vn[i];
    if (tid < EMB) sb[tid] = b[tid];

    int warp = tid >> 5, lane = tid & 31;
    const float2* cat2 = (const float2*)g_cat;
    const float2* net2 = (const float2*)g_net;
    const float2* vn2 = (const float2*)vns;

    for (int tile = blockIdx.x; tile < NTILES_NET; tile += gridDim.x) {
        long long row0 = (long long)tile * 64;
        __syncthreads();   // staging done / previous writeout done
        for (int q = 0; q < 8; q++) {
            int r = warp * 8 + q;
            long long netid = row0 + r;
            float2 acc = make_float2(0.f, 0.f);
            if (netid < MNET) {
                acc = net2[netid * 32 + lane];
                int p0 = g_off_net[netid], p1 = g_off_net[netid + 1];
                int p = p0;
                for (; p + 3 < p1; p += 4) {
                    int2 e0 = g_csr_net[p], e1 = g_csr_net[p + 1];
                    int2 e2 = g_csr_net[p + 2], e3 = g_csr_net[p + 3];
                    int n0 = e0.x & NODE_MASK, b0 = e0.x >> 19;
                    int n1 = e1.x & NODE_MASK, b1 = e1.x >> 19;
                    int n2 = e2.x & NODE_MASK, b2 = e2.x >> 19;
                    int n3 = e3.x & NODE_MASK, b3 = e3.x >> 19;
                    float2 v0 = cat2[(size_t)n0 * 128 + l * 32 + lane];
                    float2 v1 = cat2[(size_t)n1 * 128 + l * 32 + lane];
                    float2 v2 = cat2[(size_t)n2 * 128 + l * 32 + lane];
                    float2 v3 = cat2[(size_t)n3 * 128 + l * 32 + lane];
                    float2 u0 = vn2[b0 * 32 + lane];
                    float2 u1 = vn2[b1 * 32 + lane];
                    float2 u2 = vn2[b2 * 32 + lane];
                    float2 u3 = vn2[b3 * 32 + lane];
                    float w0 = __int_as_float(e0.y), w1 = __int_as_float(e1.y);
                    float w2 = __int_as_float(e2.y), w3 = __int_as_float(e3.y);
                    acc.x += w0 * (v0.x + u0.x) + w1 * (v1.x + u1.x)
                           + w2 * (v2.x + u2.x) + w3 * (v3.x + u3.x);
                    acc.y += w0 * (v0.y + u0.y) + w1 * (v1.y + u1.y)
                           + w2 * (v2.y + u2.y) + w3 * (v3.y + u3.y);
                }
                for (; p < p1; p++) {
                    int2 e0 = g_csr_net[p];
                    int n0 = e0.x & NODE_MASK, b0 = e0.x >> 19;
                    float2 v0 = cat2[(size_t)n0 * 128 + l * 32 + lane];
                    float2 u0 = vn2[b0 * 32 + lane];
                    float w0 = __int_as_float(e0.y);
                    acc.x += w0 * (v0.x + u0.x);
                    acc.y += w0 * (v0.y + u0.y);
                }
            }
            *(float2*)(As + r * CLD + 2 * lane) = acc;
        }
        __syncthreads();
        conv_mma_epilogue(As, Ws, sb, tid, row0, MNET, (float*)g_net, 16, 0);
    }
}

__global__ __launch_bounds__(256) void k_node_mma(
    const float* __restrict__ W, const float* __restrict__ b,
    const int* __restrict__ batch, int l) {
    extern __shared__ float sm[];
    float* As = sm;
    float* Ws = sm + 64 * CLD;
    float* vns = sm + 128 * CLD;
    float* sb = vns + VN * EMB;
    int tid = threadIdx.x;
    for (int i = tid; i < EMB * EMB; i += 256) Ws[(i >> 6) * CLD + (i & 63)] = W[i];
    for (int i = tid; i < VN * EMB; i += 256) vns[i] = g_vn[i];
    if (tid < EMB) sb[tid] = b[tid];

    int warp = tid >> 5, lane = tid & 31;
    const float2* cat2 = (const float2*)g_cat;
    const float2* net2 = (const float2*)g_net;
    const float2* vn2 = (const float2*)vns;

    for (int tile = blockIdx.x; tile < NTILES_NODE; tile += gridDim.x) {
        long long row0 = (long long)tile * 64;
        __syncthreads();
        for (int q = 0; q < 8; q++) {
            int r = warp * 8 + q;
            long long node = row0 + r;
            float2 acc = make_float2(0.f, 0.f);
            if (node < NCELL) {
                int bb = batch[node];
                float2 v = cat2[node * 128 + l * 32 + lane];
                float2 u = vn2[bb * 32 + lane];
                acc.x = v.x + u.x; acc.y = v.y + u.y;
                int p0 = g_off_node[node], p1 = g_off_node[node + 1];
                int p = p0;
                for (; p + 3 < p1; p += 4) {
                    int2 e0 = g_csr_node[p], e1 = g_csr_node[p + 1];
                    int2 e2 = g_csr_node[p + 2], e3 = g_csr_node[p + 3];
                    float2 v0 = net2[(size_t)e0.x * 32 + lane];
                    float2 v1 = net2[(size_t)e1.x * 32 + lane];
                    float2 v2 = net2[(size_t)e2.x * 32 + lane];
                    float2 v3 = net2[(size_t)e3.x * 32 + lane];
                    float w0 = __int_as_float(e0.y), w1 = __int_as_float(e1.y);
                    float w2 = __int_as_float(e2.y), w3 = __int_as_float(e3.y);
                    acc.x += w0 * v0.x + w1 * v1.x + w2 * v2.x + w3 * v3.x;
                    acc.y += w0 * v0.y + w1 * v1.y + w2 * v2.y + w3 * v3.y;
                }
                for (; p < p1; p++) {
                    int2 e0 = g_csr_node[p];
                    float2 v0 = net2[(size_t)e0.x * 32 + lane];
                    float w0 = __int_as_float(e0.y);
                    acc.x += w0 * v0.x; acc.y += w0 * v0.y;
                }
            }
            *(float2*)(As + r * CLD + 2 * lane) = acc;
        }
        __syncthreads();
        conv_mma_epilogue(As, Ws, sb, tid, row0, NCELL, (float*)g_cat, 64, (l + 1) * 16);
    }
}

// ---------------- head: 128 rows x 256 cols, 512 threads ----------------
#define AS_LD 68
#define BS_LD 260
#define HS_LD 260
#define DSMEM_HEAD (128 * HS_LD * 4)   // 133120 >= (128*AS_LD + 64*BS_LD)*4

__global__ __launch_bounds__(512) void k_head_mma(
    const float* __restrict__ fc1w, const float* __restrict__ fc1b,
    const float* __restrict__ fc2w, const float* __restrict__ fc2b,
    const float* __restrict__ outw, const float* __restrict__ outb,
    const float* __restrict__ cat,
    float* __restrict__ nodes_out, float* __restrict__ ret_out) {
    extern __shared__ float sm[];
    float* As = sm;                   // [128][AS_LD]
    float* Bs = sm + 128 * AS_LD;     // [64][BS_LD]
    float* Hs = sm;                   // [128][HS_LD] (aliases after fc1)
    __shared__ float s_ow[CATD];
    __shared__ float s_fc2[8 * 256];
    __shared__ float rpart4[128][4];

    int tid = threadIdx.x;
    int warp = tid >> 5, lane = tid & 31;
    int gid = lane >> 2, tig = lane & 3;
    int mrow0 = (warp >> 2) * 32;     // 4 M-groups of 32 rows
    int ncol0 = (warp & 3) * 64;      // 4 N-groups of 64 cols
    size_t n0 = (size_t)blockIdx.x * 128;

    if (tid < CATD) s_ow[tid] = outw[tid];
    for (int i = tid; i < 2048; i += 512) {
        int o = i >> 8, jj = i & 255;
        s_fc2[o * 256 + jj] = fc2w[jj * 8 + o];
    }
    { int r = tid >> 2, q = tid & 3; rpart4[r][q] = 0.f; }

    float c[2][8][4];
    #pragma unroll
    for (int mf = 0; mf < 2; mf++)
        #pragma unroll
        for (int nt = 0; nt < 8; nt++)
            #pragma unroll
            for (int q = 0; q < 4; q++) c[mf][nt][q] = 0.f;

    for (int kc = 0; kc < 4; kc++) {
        __syncthreads();
        // stage A: 128x64 = 2048 float4
        #pragma unroll
        for (int q = 0; q < 4; q++) {
            int idx = q * 512 + tid;
            int r = idx >> 4, k4 = idx & 15;
            size_t row = n0 + r;
            float4 v = (row < NCELL)
                ? *(const float4*)(cat + row * CATD + kc * 64 + k4 * 4)
                : make_float4(0.f, 0.f, 0.f, 0.f);
            *(float4*)(As + r * AS_LD + k4 * 4) = v;
        }
        // stage B: 64x256 = 4096 float4
        #pragma unroll
        for (int q = 0; q < 8; q++) {
            int idx = q * 512 + tid;
            int r = idx >> 6, j4 = idx & 63;
            float4 v = *(const float4*)(fc1w + (size_t)(kc * 64 + r) * 256 + j4 * 4);
            *(float4*)(Bs + r * BS_LD + j4 * 4) = v;
        }
        __syncthreads();
        // ret partial: r = tid>>2 (0..127), q = tid&3
        {
            int r = tid >> 2, q = tid & 3;
            float a = 0.f;
            #pragma unroll
            for (int kk = 0; kk < 16; kk++)
                a += As[r * AS_LD + q * 16 + kk] * s_ow[kc * 64 + q * 16 + kk];
            rpart4[r][q] += a;
        }
        #pragma unroll
        for (int kk = 0; kk < 8; kk++) {
            int kb = kk * 8;
            uint32_t a[2][4];
            #pragma unroll
            for (int mf = 0; mf < 2; mf++) {
                int rb = mrow0 + mf * 16;
                a[mf][0] = f2tf32(As[(rb + gid) * AS_LD + kb + tig]);
                a[mf][1] = f2tf32(As[(rb + gid + 8) * AS_LD + kb + tig]);
                a[mf][2] = f2tf32(As[(rb + gid) * AS_LD + kb + tig + 4]);
                a[mf][3] = f2tf32(As[(rb + gid + 8) * AS_LD + kb + tig + 4]);
            }
            #pragma unroll
            for (int nt = 0; nt < 8; nt++) {
                int col = ncol0 + nt * 8 + gid;
                uint32_t b0 = f2tf32(Bs[(kb + tig) * BS_LD + col]);
                uint32_t b1 = f2tf32(Bs[(kb + tig + 4) * BS_LD + col]);
                mma_tf32(c[0][nt], a[0][0], a[0][1], a[0][2], a[0][3], b0, b1);
                mma_tf32(c[1][nt], a[1][0], a[1][1], a[1][2], a[1][3], b0, b1);
            }
        }
    }
    __syncthreads();
    #pragma unroll
    for (int mf = 0; mf < 2; mf++) {
        int rb = mrow0 + mf * 16;
        #pragma unroll
        for (int nt = 0; nt < 8; nt++) {
            int col0 = ncol0 + nt * 8 + 2 * tig;
            float bb0 = fc1b[col0], bb1 = fc1b[col0 + 1];
            Hs[(rb + gid) * HS_LD + col0]     = fmaxf(c[mf][nt][0] + bb0, 0.f);
            Hs[(rb + gid) * HS_LD + col0 + 1] = fmaxf(c[mf][nt][1] + bb1, 0.f);
            Hs[(rb + gid + 8) * HS_LD + col0]     = fmaxf(c[mf][nt][2] + bb0, 0.f);
            Hs[(rb + gid + 8) * HS_LD + col0 + 1] = fmaxf(c[mf][nt][3] + bb1, 0.f);
        }
    }
    __syncthreads();
    // fc2: 128 rows x 8 outs = 1024 pairs, 2 per thread
    #pragma unroll
    for (int pp = 0; pp < 2; pp++) {
        int p = tid + pp * 512;
        int r = p >> 3, o = p & 7;
        size_t row = n0 + r;
        float a = fc2b[o];
        const float4* h4 = (const float4*)(Hs + r * HS_LD);
        const float4* w4 = (const float4*)(s_fc2 + o * 256);
        #pragma unroll 8
        for (int jj = 0; jj < 64; jj++) {
            float4 h = h4[jj], w = w4[jj];
            a += h.x * w.x + h.y * w.y + h.z * w.z + h.w * w.w;
        }
        if (row < NCELL) nodes_out[row * OUTD + o] = fmaxf(a, 0.f);
    }
    if (tid < 128) {
        size_t row = n0 + tid;
        if (row < NCELL) {
            float s = outb[0] + rpart4[tid][0] + rpart4[tid][1] + rpart4[tid][2] + rpart4[tid][3];
            ret_out[row] = s;
        }
    }
}

// ---------------- launch ----------------
static inline int cdiv(long long a, long long b) { return (int)((a + b - 1) / b); }

extern "C" void kernel_launch(void* const* d_in, const int* in_sizes, int n_in,
                              void* d_out, int out_size) {
    const float* node_f     = (const float*)d_in[0];
    const float* net_f      = (const float*)d_in[1];
    const int*   sink_node  = (const int*)d_in[2];
    const int*   sink_net   = (const int*)d_in[3];
    const int*   src_node   = (const int*)d_in[4];
    const int*   src_net    = (const int*)d_in[5];
    const int*   batch      = (const int*)d_in[6];
    const float* w_node     = (const float*)d_in[8];
    const float* b_node     = (const float*)d_in[9];
    const float* w_net      = (const float*)d_in[10];
    const float* b_net      = (const float*)d_in[11];
    const float* vn_emb     = (const float*)d_in[12];
    const float* vn_mlp_w   = (const float*)d_in[13];
    const float* vn_mlp_b   = (const float*)d_in[14];
    const float* conv_net_w = (const float*)d_in[15];
    const float* conv_net_b = (const float*)d_in[16];
    const float* conv_node_w= (const float*)d_in[17];
    const float* conv_node_b= (const float*)d_in[18];
    const float* fc1_w      = (const float*)d_in[19];
    const float* fc1_b      = (const float*)d_in[20];
    const float* fc2_w      = (const float*)d_in[21];
    const float* fc2_b      = (const float*)d_in[22];
    const float* out_w      = (const float*)d_in[23];
    const float* out_b      = (const float*)d_in[24];

    static bool attr_done = false;
    if (!attr_done) {
        cudaFuncSetAttribute(k_head_mma, cudaFuncAttributeMaxDynamicSharedMemorySize, DSMEM_HEAD);
        cudaFuncSetAttribute(k_net_mma, cudaFuncAttributeMaxDynamicSharedMemorySize, DSMEM_CONV);
        cudaFuncSetAttribute(k_node_mma, cudaFuncAttributeMaxDynamicSharedMemorySize, DSMEM_CONV);
        attr_done = true;
    }

    int *p_cnt_n, *p_cnt_comb, *p_off_net, *p_cur_net, *p_off_node, *p_cur_node;
    float *p_cat, *p_net;
    cudaGetSymbolAddress((void**)&p_cnt_n, g_cnt_n);
    cudaGetSymbolAddress((void**)&p_cnt_comb, g_cnt_comb);
    cudaGetSymbolAddress((void**)&p_off_net, g_off_net);
    cudaGetSymbolAddress((void**)&p_cur_net, g_cur_net);
    cudaGetSymbolAddress((void**)&p_off_node, g_off_node);
    cudaGetSymbolAddress((void**)&p_cur_node, g_cur_node);
    cudaGetSymbolAddress((void**)&p_cat, g_cat);
    cudaGetSymbolAddress((void**)&p_net, g_net);

    // 1-5: setup + embeds
    k_zero_all<<<cdiv(NCELL, 256), 256>>>();
    k_count<<<cdiv(EKE, 256), 256>>>(sink_node, sink_net, src_net);
    k_addcnt_rsq<<<cdiv(NCELL, 256), 256>>>();
    k_embed<<<cdiv(NCELL, 16), 256>>>(node_f, w_node, b_node, p_cat, NCELL, CATD);
    k_embed<<<cdiv(MNET, 16), 256>>>(net_f, w_net, b_net, p_net, MNET, EMB);
    // 6: pool for layer 0 (ncu capture slot)
    k_pool_cat<<<512, 256>>>(batch, 0);
    // 7: vn counts
    k_cnt<<<128, 256>>>(batch);

    // CSR by net
    {
        int nb = cdiv(MNET, 1024);
        k_scan1<<<nb, 256>>>(p_cnt_comb, MNET);
        k_scan2<<<1, 1024>>>(nb);
        k_scan3<<<nb, 256>>>(p_cnt_comb, MNET, p_off_net, p_cur_net);
        k_sentinel<<<1, 1>>>(p_off_net, MNET, ECOMB);
    }
    // CSR by node
    {
        int nb = cdiv(NCELL, 1024);
        k_scan1<<<nb, 256>>>(p_cnt_n, NCELL);
        k_scan2<<<1, 1024>>>(nb);
        k_scan3<<<nb, 256>>>(p_cnt_n, NCELL, p_off_node, p_cur_node);
        k_sentinel<<<1, 1>>>(p_off_node, NCELL, EKE);
    }
    k_scat_net_src<<<cdiv(ESE, 256), 256>>>(src_node, src_net, batch);
    k_scat_sink<<<cdiv(EKE, 256), 256>>>(sink_node, sink_net, batch);
    k_vninit<<<cdiv(VN * EMB, 256), 256>>>(vn_emb);

    // layers (pool(0) already done at slot 6)
    for (int l = 0; l < NL; l++) {
        k_net_mma<<<CONV_GRID, 256, DSMEM_CONV>>>(conv_net_w + l * 4096, conv_net_b + l * 64, l);
        k_node_mma<<<CONV_GRID, 256, DSMEM_CONV>>>(conv_node_w + l * 4096, conv_node_b + l * 64, batch, l);
        if (l < NL - 1) {
            k_vn<<<VN, EMB>>>(vn_mlp_w + l * 4096, vn_mlp_b + l * 64);
            if (l + 1 < NL - 1)
                k_pool_cat<<<512, 256>>>(batch, l + 1);
        }
    }
    // NOTE: pool for l=1 must run after node_mma(0) and before k_vn(1):
    // handled above: at l=0 iteration, k_vn(0) then k_pool_cat(l=1).

    // head
    float* nodes_out = (float*)d_out;
    float* ret_out = (float*)d_out + (size_t)NCELL * OUTD;
    k_head_mma<<<cdiv(NCELL, 128), 512, DSMEM_HEAD>>>(fc1_w, fc1_b, fc2_w, fc2_b,
                                                      out_w, out_b, p_cat, nodes_out, ret_out);
}

// round 8
// speedup vs baseline: 2.3556x; 1.0407x over previous
#include <cuda_runtime.h>
#include <cstdint>

#define NCELL 500000
#define MNET  450000
#define EKE   2000000
#define ESE   500000
#define ECOMB (EKE + ESE)
#define EMB   64
#define VN    64
#define NL    3
#define CATD  256
#define OUTD  8
#define NODE_MASK 0x7FFFF
#define SCAN_TOT (MNET + NCELL)

// ---------------- scratch ----------------
__device__ int   g_cnt_n[NCELL];
__device__ int   g_cnt_e[MNET];
__device__ int   g_cnt_comb[MNET];
__device__ int   g_off_net[MNET + 1];
__device__ int   g_cur_net[MNET];
__device__ int   g_off_node[NCELL + 1];
__device__ int   g_cur_node[NCELL];
__device__ int2  g_csr_net[ECOMB];     // (packed node|b<<19, weight bits)
__device__ int2  g_csr_node[EKE];      // (net, weight bits)
__device__ int   g_partial[1024];
__device__ float g_rsq_n[NCELL];
__device__ float g_rsq_e[MNET];
__device__ float g_cat[(size_t)NCELL * CATD];
__device__ float g_net[(size_t)MNET * EMB];
__device__ float g_vn[VN * EMB];
__device__ float g_pool[VN * EMB];   // invariant: zero at kernel_launch entry
__device__ float g_cntvn[VN];

// ---------------- helpers ----------------
__device__ __forceinline__ uint32_t f2tf32(float v) {
    uint32_t r; asm("cvt.rna.tf32.f32 %0, %1;" : "=r"(r) : "f"(v)); return r;
}
__device__ __forceinline__ void split_tf32(float v, uint32_t& hi, uint32_t& lo) {
    hi = f2tf32(v);
    lo = f2tf32(v - __uint_as_float(hi));
}
__device__ __forceinline__ void mma_tf32(float* c, uint32_t a0, uint32_t a1, uint32_t a2,
                                         uint32_t a3, uint32_t b0, uint32_t b1) {
    asm("mma.sync.aligned.m16n8k8.row.col.f32.tf32.tf32.f32 "
        "{%0,%1,%2,%3},{%4,%5,%6,%7},{%8,%9},{%0,%1,%2,%3};"
        : "+f"(c[0]), "+f"(c[1]), "+f"(c[2]), "+f"(c[3])
        : "r"(a0), "r"(a1), "r"(a2), "r"(a3), "r"(b0), "r"(b1));
}

// ---------------- setup ----------------
__global__ void k_zero_all() {
    int i = blockIdx.x * blockDim.x + threadIdx.x;
    if (i < NCELL) g_cnt_n[i] = 0;
    if (i < MNET) { g_cnt_e[i] = 0; g_cnt_comb[i] = 0; }
    if (i < VN) g_cntvn[i] = 0.f;
}
__global__ void k_count(const int* __restrict__ sn, const int* __restrict__ se,
                        const int* __restrict__ src_net) {
    int i = blockIdx.x * blockDim.x + threadIdx.x;
    if (i < EKE) { atomicAdd(&g_cnt_n[sn[i]], 1); atomicAdd(&g_cnt_e[se[i]], 1); }
    if (i < ESE) atomicAdd(&g_cnt_comb[src_net[i]], 1);
}
// cnt_comb += cnt_e; rsq; vninit; batch histogram
__global__ void k_prep(const int* __restrict__ batch, const float* __restrict__ vn_emb) {
    __shared__ float hist[VN];
    int tid = threadIdx.x;
    int i = blockIdx.x * blockDim.x + tid;
    if (tid < VN) hist[tid] = 0.f;
    __syncthreads();
    if (i < MNET) {
        int ce = g_cnt_e[i];
        g_cnt_comb[i] += ce;
        g_rsq_e[i] = rsqrtf(fmaxf((float)ce, 1.f));
    }
    if (i < NCELL) {
        g_rsq_n[i] = rsqrtf(fmaxf((float)g_cnt_n[i], 1.f));
        atomicAdd(&hist[batch[i]], 1.f);
    }
    if (i < VN * EMB) g_vn[i] = vn_emb[i & 63];
    __syncthreads();
    if (tid < VN) atomicAdd(&g_cntvn[tid], hist[tid]);
}

// ---------------- combined exclusive scan over [cnt_comb | cnt_n] ----------------
__device__ __forceinline__ int comb_cnt(int i) {
    return (i < MNET) ? g_cnt_comb[i] : g_cnt_n[i - MNET];
}
__global__ void k_scan1() {
    __shared__ int s[256];
    int base = blockIdx.x * 1024, t = threadIdx.x;
    int sum = 0;
    #pragma unroll
    for (int q = 0; q < 4; q++) { int i = base + q * 256 + t; sum += (i < SCAN_TOT) ? comb_cnt(i) : 0; }
    s[t] = sum; __syncthreads();
    for (int st = 128; st > 0; st >>= 1) {
        if (t < st) s[t] += s[t + st];
        __syncthreads();
    }
    if (t == 0) g_partial[blockIdx.x] = s[0];
}
__global__ void k_scan2(int nb) {
    __shared__ int s[1024];
    int t = threadIdx.x;
    int v = (t < nb) ? g_partial[t] : 0;
    s[t] = v; __syncthreads();
    for (int st = 1; st < 1024; st <<= 1) {
        int a = (t >= st) ? s[t - st] : 0;
        __syncthreads();
        s[t] += a; __syncthreads();
    }
    if (t < nb) g_partial[t] = s[t] - v;
}
__global__ void k_scan3() {
    __shared__ int s[256];
    int t = threadIdx.x, base = blockIdx.x * 1024;
    int v[4], sum = 0;
    #pragma unroll
    for (int q = 0; q < 4; q++) { int i = base + t * 4 + q; v[q] = (i < SCAN_TOT) ? comb_cnt(i) : 0; sum += v[q]; }
    s[t] = sum; __syncthreads();
    int mine = sum;
    for (int st = 1; st < 256; st <<= 1) {
        int a = (t >= st) ? s[t - st] : 0;
        __syncthreads();
        s[t] += a; __syncthreads();
    }
    int ex = s[t] - mine + g_partial[blockIdx.x];
    #pragma unroll
    for (int q = 0; q < 4; q++) {
        int i = base + t * 4 + q;
        if (i < SCAN_TOT) {
            if (i < MNET) { g_off_net[i] = ex; g_cur_net[i] = ex; }
            else { g_off_node[i - MNET] = ex - ECOMB; g_cur_node[i - MNET] = ex - ECOMB; }
            ex += v[q];
        }
    }
    if (blockIdx.x == 0 && t == 0) {
        g_off_net[MNET] = ECOMB;
        g_off_node[NCELL] = EKE;
    }
}

// ---------------- combined CSR scatter ----------------
__global__ void k_scat(const int* __restrict__ sink_node, const int* __restrict__ sink_net,
                       const int* __restrict__ src_node, const int* __restrict__ src_net,
                       const int* __restrict__ batch) {
    int e = blockIdx.x * blockDim.x + threadIdx.x;
    if (e < EKE) {
        int node = sink_node[e], net = sink_net[e];
        float ew = g_rsq_n[node] * g_rsq_e[net];
        int packed = node | (batch[node] << 19);
        int pn = atomicAdd(&g_cur_net[net], 1);
        g_csr_net[pn] = make_int2(packed, __float_as_int(ew));
        int pd = atomicAdd(&g_cur_node[node], 1);
        g_csr_node[pd] = make_int2(net, __float_as_int(ew));
    }
    if (e < ESE) {
        int node = src_node[e];
        int packed = node | (batch[node] << 19);
        int pos = atomicAdd(&g_cur_net[src_net[e]], 1);
        g_csr_net[pos] = make_int2(packed, __float_as_int(1.f));
    }
}

// ---------------- embedding: relu(feat[16] @ W[16,64] + b), smem-staged, reg weights ----------------
// block = 256 threads, 32 rows; optional fused VN pooling of the output
__global__ __launch_bounds__(256) void k_embed(
    const float* __restrict__ feat, const float* __restrict__ w, const float* __restrict__ b,
    float* __restrict__ out, int nrows, int ostride,
    int doPool, const int* __restrict__ batch) {
    __shared__ float s_w[16 * EMB];
    __shared__ float s_in[32][17];
    __shared__ int   s_batch[32];
    __shared__ float s_pool[VN * EMB];
    int tid = threadIdx.x;
    int j = tid & 63, rq = tid >> 6;
    int base = blockIdx.x * 32;

    for (int i = tid; i < 16 * EMB; i += 256) s_w[i] = w[i];
    if (doPool) for (int i = tid; i < VN * EMB; i += 256) s_pool[i] = 0.f;
    // stage features (float4): 32 rows x 4 float4
    if (tid < 128) {
        int r = tid >> 2, k4 = tid & 3;
        int row = base + r;
        float4 v = (row < nrows) ? ((const float4*)feat)[(size_t)row * 4 + k4]
                                 : make_float4(0.f, 0.f, 0.f, 0.f);
        s_in[r][k4 * 4 + 0] = v.x; s_in[r][k4 * 4 + 1] = v.y;
        s_in[r][k4 * 4 + 2] = v.z; s_in[r][k4 * 4 + 3] = v.w;
    }
    if (doPool && tid < 32) {
        int row = base + tid;
        s_batch[tid] = (row < nrows) ? batch[row] : 0;
    }
    float breg = b[j];
    __syncthreads();

    float wreg[16];
    #pragma unroll
    for (int k = 0; k < 16; k++) wreg[k] = s_w[k * EMB + j];

    #pragma unroll
    for (int s = 0; s < 8; s++) {
        int r = rq + s * 4;
        int row = base + r;
        if (row < nrows) {
            float a = breg;
            #pragma unroll
            for (int k = 0; k < 16; k++) a += s_in[r][k] * wreg[k];
            a = fmaxf(a, 0.f);
            out[(size_t)row * ostride + j] = a;
            if (doPool) atomicAdd(&s_pool[s_batch[r] * EMB + j], a);
        }
    }
    if (doPool) {
        __syncthreads();
        for (int i = tid; i < VN * EMB; i += 256) atomicAdd(&g_pool[i], s_pool[i]);
    }
}

// ---------------- VN pooling from cat ----------------
__global__ void k_pool_cat(const int* __restrict__ batch, int l) {
    __shared__ float s[VN * EMB];
    int tid = threadIdx.x;
    for (int i = tid; i < VN * EMB; i += 256) s[i] = 0.f;
    __syncthreads();
    int c0 = (tid & 15) * 4, r = tid >> 4;
    for (long long n = (long long)blockIdx.x * 16 + r; n < NCELL; n += (long long)gridDim.x * 16) {
        int b = batch[n];
        float4 v = *(const float4*)&g_cat[n * CATD + l * EMB + c0];
        atomicAdd(&s[b * EMB + c0 + 0], v.x);
        atomicAdd(&s[b * EMB + c0 + 1], v.y);
        atomicAdd(&s[b * EMB + c0 + 2], v.z);
        atomicAdd(&s[b * EMB + c0 + 3], v.w);
    }
    __syncthreads();
    for (int i = tid; i < VN * EMB; i += 256) atomicAdd(&g_pool[i], s[i]);
}

// ---------------- VN update (re-zeros g_pool) ----------------
__global__ void k_vn(const float* __restrict__ w, const float* __restrict__ b) {
    int v = blockIdx.x, j = threadIdx.x;
    __shared__ float t[EMB];
    float cnt = g_cntvn[v];
    float vv = g_vn[v * EMB + j];
    t[j] = (g_pool[v * EMB + j] + cnt * vv) / fmaxf(cnt, 1.f) + vv;
    g_pool[v * EMB + j] = 0.f;
    __syncthreads();
    float acc = b[j];
    #pragma unroll
    for (int k = 0; k < EMB; k++) acc += t[k] * w[k * EMB + j];
    g_vn[v * EMB + j] = vv + fmaxf(acc, 0.f);
}

// =====================================================================
// Persistent fused gather + 3xTF32 mma conv kernels
// =====================================================================
#define CLD 68
#define DSMEM_NET  ((64 * CLD + 64 * CLD + VN * EMB + EMB) * 4)
#define DSMEM_NODE ((64 * CLD + 64 * CLD + EMB) * 4)
#define CONV_GRID 592
#define NTILES_NET  ((MNET + 63) / 64)
#define NTILES_NODE ((NCELL + 63) / 64)

__device__ __forceinline__ void conv_mma_epilogue(
    float* As, float* Ws, const float* sb,
    int tid, long long row0, int nrows, float* __restrict__ outbuf,
    int ostride4, int ooff4)
{
    int warp = tid >> 5, lane = tid & 31;
    int gid = lane >> 2, tig = lane & 3;
    int mrow0 = (warp >> 1) * 16;
    int ncol0 = (warp & 1) * 32;

    float c[4][4];
    #pragma unroll
    for (int nt = 0; nt < 4; nt++)
        #pragma unroll
        for (int q = 0; q < 4; q++) c[nt][q] = 0.f;

    #pragma unroll
    for (int kk = 0; kk < 8; kk++) {
        int kb = kk * 8;
        uint32_t ah0, al0, ah1, al1, ah2, al2, ah3, al3;
        split_tf32(As[(mrow0 + gid) * CLD + kb + tig], ah0, al0);
        split_tf32(As[(mrow0 + gid + 8) * CLD + kb + tig], ah1, al1);
        split_tf32(As[(mrow0 + gid) * CLD + kb + tig + 4], ah2, al2);
        split_tf32(As[(mrow0 + gid + 8) * CLD + kb + tig + 4], ah3, al3);
        #pragma unroll
        for (int nt = 0; nt < 4; nt++) {
            int col = ncol0 + nt * 8 + gid;
            uint32_t bh0, bl0, bh1, bl1;
            split_tf32(Ws[(kb + tig) * CLD + col], bh0, bl0);
            split_tf32(Ws[(kb + tig + 4) * CLD + col], bh1, bl1);
            mma_tf32(c[nt], ah0, ah1, ah2, ah3, bh0, bh1);
            mma_tf32(c[nt], ah0, ah1, ah2, ah3, bl0, bl1);
            mma_tf32(c[nt], al0, al1, al2, al3, bh0, bh1);
        }
    }
    __syncthreads();
    #pragma unroll
    for (int nt = 0; nt < 4; nt++) {
        int col0 = ncol0 + nt * 8 + 2 * tig;
        float b0 = sb[col0], b1 = sb[col0 + 1];
        As[(mrow0 + gid) * CLD + col0]     = fmaxf(c[nt][0] + b0, 0.f);
        As[(mrow0 + gid) * CLD + col0 + 1] = fmaxf(c[nt][1] + b1, 0.f);
        As[(mrow0 + gid + 8) * CLD + col0]     = fmaxf(c[nt][2] + b0, 0.f);
        As[(mrow0 + gid + 8) * CLD + col0 + 1] = fmaxf(c[nt][3] + b1, 0.f);
    }
    __syncthreads();
    #pragma unroll
    for (int q = 0; q < 4; q++) {
        int idx = q * 256 + tid;
        int r = idx >> 4, c4 = idx & 15;
        long long row = row0 + r;
        if (row < nrows) {
            float4 v = *(const float4*)(As + r * CLD + c4 * 4);
            ((float4*)outbuf)[row * ostride4 + ooff4 + c4] = v;
        }
    }
}

__global__ __launch_bounds__(256) void k_net_mma(
    const float* __restrict__ W, const float* __restrict__ b, int l) {
    extern __shared__ float sm[];
    float* As = sm;
    float* Ws = sm + 64 * CLD;
    float* vns = sm + 128 * CLD;
    float* sb = vns + VN * EMB;
    int tid = threadIdx.x;
    for (int i = tid; i < EMB * EMB; i += 256) Ws[(i >> 6) * CLD + (i & 63)] = W[i];
    for (int i = tid; i < VN * EMB; i += 256) vns[i] = g_vn[i];
    if (tid < EMB) sb[tid] = b[tid];

    int warp = tid >> 5, lane = tid & 31;
    const float2* cat2 = (const float2*)g_cat;
    const float2* net2 = (const float2*)g_net;
    const float2* vn2 = (const float2*)vns;

    for (int tile = blockIdx.x; tile < NTILES_NET; tile += gridDim.x) {
        long long row0 = (long long)tile * 64;
        __syncthreads();
        for (int q = 0; q < 8; q++) {
            int r = warp * 8 + q;
            long long netid = row0 + r;
            float2 acc = make_float2(0.f, 0.f);
            if (netid < MNET) {
                acc = net2[netid * 32 + lane];
                int p0 = g_off_net[netid], p1 = g_off_net[netid + 1];
                int p = p0;
                for (; p + 3 < p1; p += 4) {
                    int2 e0 = g_csr_net[p], e1 = g_csr_net[p + 1];
                    int2 e2 = g_csr_net[p + 2], e3 = g_csr_net[p + 3];
                    int n0 = e0.x & NODE_MASK, b0 = e0.x >> 19;
                    int n1 = e1.x & NODE_MASK, b1 = e1.x >> 19;
                    int n2 = e2.x & NODE_MASK, b2 = e2.x >> 19;
                    int n3 = e3.x & NODE_MASK, b3 = e3.x >> 19;
                    float2 v0 = cat2[(size_t)n0 * 128 + l * 32 + lane];
                    float2 v1 = cat2[(size_t)n1 * 128 + l * 32 + lane];
                    float2 v2 = cat2[(size_t)n2 * 128 + l * 32 + lane];
                    float2 v3 = cat2[(size_t)n3 * 128 + l * 32 + lane];
                    float2 u0 = vn2[b0 * 32 + lane];
                    float2 u1 = vn2[b1 * 32 + lane];
                    float2 u2 = vn2[b2 * 32 + lane];
                    float2 u3 = vn2[b3 * 32 + lane];
                    float w0 = __int_as_float(e0.y), w1 = __int_as_float(e1.y);
                    float w2 = __int_as_float(e2.y), w3 = __int_as_float(e3.y);
                    acc.x += w0 * (v0.x + u0.x) + w1 * (v1.x + u1.x)
                           + w2 * (v2.x + u2.x) + w3 * (v3.x + u3.x);
                    acc.y += w0 * (v0.y + u0.y) + w1 * (v1.y + u1.y)
                           + w2 * (v2.y + u2.y) + w3 * (v3.y + u3.y);
                }
                for (; p < p1; p++) {
                    int2 e0 = g_csr_net[p];
                    int n0 = e0.x & NODE_MASK, b0 = e0.x >> 19;
                    float2 v0 = cat2[(size_t)n0 * 128 + l * 32 + lane];
                    float2 u0 = vn2[b0 * 32 + lane];
                    float w0 = __int_as_float(e0.y);
                    acc.x += w0 * (v0.x + u0.x);
                    acc.y += w0 * (v0.y + u0.y);
                }
            }
            *(float2*)(As + r * CLD + 2 * lane) = acc;
        }
        __syncthreads();
        conv_mma_epilogue(As, Ws, sb, tid, row0, MNET, (float*)g_net, 16, 0);
    }
}

__global__ __launch_bounds__(256) void k_node_mma(
    const float* __restrict__ W, const float* __restrict__ b,
    const int* __restrict__ batch, int l) {
    extern __shared__ float sm[];
    float* As = sm;
    float* Ws = sm + 64 * CLD;
    float* sb = sm + 128 * CLD;
    int tid = threadIdx.x;
    for (int i = tid; i < EMB * EMB; i += 256) Ws[(i >> 6) * CLD + (i & 63)] = W[i];
    if (tid < EMB) sb[tid] = b[tid];

    int warp = tid >> 5, lane = tid & 31;
    const float2* cat2 = (const float2*)g_cat;
    const float2* net2 = (const float2*)g_net;
    const float2* vn2 = (const float2*)g_vn;

    for (int tile = blockIdx.x; tile < NTILES_NODE; tile += gridDim.x) {
        long long row0 = (long long)tile * 64;
        __syncthreads();
        for (int q = 0; q < 8; q++) {
            int r = warp * 8 + q;
            long long node = row0 + r;
            float2 acc = make_float2(0.f, 0.f);
            if (node < NCELL) {
                int bb = batch[node];
                float2 v = cat2[node * 128 + l * 32 + lane];
                float2 u = vn2[bb * 32 + lane];
                acc.x = v.x + u.x; acc.y = v.y + u.y;
                int p0 = g_off_node[node], p1 = g_off_node[node + 1];
                int p = p0;
                for (; p + 3 < p1; p += 4) {
                    int2 e0 = g_csr_node[p], e1 = g_csr_node[p + 1];
                    int2 e2 = g_csr_node[p + 2], e3 = g_csr_node[p + 3];
                    float2 v0 = net2[(size_t)e0.x * 32 + lane];
                    float2 v1 = net2[(size_t)e1.x * 32 + lane];
                    float2 v2 = net2[(size_t)e2.x * 32 + lane];
                    float2 v3 = net2[(size_t)e3.x * 32 + lane];
                    float w0 = __int_as_float(e0.y), w1 = __int_as_float(e1.y);
                    float w2 = __int_as_float(e2.y), w3 = __int_as_float(e3.y);
                    acc.x += w0 * v0.x + w1 * v1.x + w2 * v2.x + w3 * v3.x;
                    acc.y += w0 * v0.y + w1 * v1.y + w2 * v2.y + w3 * v3.y;
                }
                for (; p < p1; p++) {
                    int2 e0 = g_csr_node[p];
                    float2 v0 = net2[(size_t)e0.x * 32 + lane];
                    float w0 = __int_as_float(e0.y);
                    acc.x += w0 * v0.x; acc.y += w0 * v0.y;
                }
            }
            *(float2*)(As + r * CLD + 2 * lane) = acc;
        }
        __syncthreads();
        conv_mma_epilogue(As, Ws, sb, tid, row0, NCELL, (float*)g_cat, 64, (l + 1) * 16);
    }
}

// ---------------- head: 128 rows x 256 cols, 512 threads ----------------
#define AS_LD 68
#define BS_LD 260
#define HS_LD 260
#define DSMEM_HEAD (128 * HS_LD * 4)

__global__ __launch_bounds__(512) void k_head_mma(
    const float* __restrict__ fc1w, const float* __restrict__ fc1b,
    const float* __restrict__ fc2w, const float* __restrict__ fc2b,
    const float* __restrict__ outw, const float* __restrict__ outb,
    const float* __restrict__ cat,
    float* __restrict__ nodes_out, float* __restrict__ ret_out) {
    extern __shared__ float sm[];
    float* As = sm;
    float* Bs = sm + 128 * AS_LD;
    float* Hs = sm;
    __shared__ float s_ow[CATD];
    __shared__ float s_fc2[8 * 256];
    __shared__ float rpart4[128][4];

    int tid = threadIdx.x;
    int warp = tid >> 5, lane = tid & 31;
    int gid = lane >> 2, tig = lane & 3;
    int mrow0 = (warp >> 2) * 32;
    int ncol0 = (warp & 3) * 64;
    size_t n0 = (size_t)blockIdx.x * 128;

    if (tid < CATD) s_ow[tid] = outw[tid];
    for (int i = tid; i < 2048; i += 512) {
        int o = i >> 8, jj = i & 255;
        s_fc2[o * 256 + jj] = fc2w[jj * 8 + o];
    }
    { int r = tid >> 2, q = tid & 3; rpart4[r][q] = 0.f; }

    float c[2][8][4];
    #pragma unroll
    for (int mf = 0; mf < 2; mf++)
        #pragma unroll
        for (int nt = 0; nt < 8; nt++)
            #pragma unroll
            for (int q = 0; q < 4; q++) c[mf][nt][q] = 0.f;

    for (int kc = 0; kc < 4; kc++) {
        __syncthreads();
        #pragma unroll
        for (int q = 0; q < 4; q++) {
            int idx = q * 512 + tid;
            int r = idx >> 4, k4 = idx & 15;
            size_t row = n0 + r;
            float4 v = (row < NCELL)
                ? *(const float4*)(cat + row * CATD + kc * 64 + k4 * 4)
                : make_float4(0.f, 0.f, 0.f, 0.f);
            *(float4*)(As + r * AS_LD + k4 * 4) = v;
        }
        #pragma unroll
        for (int q = 0; q < 8; q++) {
            int idx = q * 512 + tid;
            int r = idx >> 6, j4 = idx & 63;
            float4 v = *(const float4*)(fc1w + (size_t)(kc * 64 + r) * 256 + j4 * 4);
            *(float4*)(Bs + r * BS_LD + j4 * 4) = v;
        }
        __syncthreads();
        {
            int r = tid >> 2, q = tid & 3;
            float a = 0.f;
            #pragma unroll
            for (int kk = 0; kk < 16; kk++)
                a += As[r * AS_LD + q * 16 + kk] * s_ow[kc * 64 + q * 16 + kk];
            rpart4[r][q] += a;
        }
        #pragma unroll
        for (int kk = 0; kk < 8; kk++) {
            int kb = kk * 8;
            uint32_t a[2][4];
            #pragma unroll
            for (int mf = 0; mf < 2; mf++) {
                int rb = mrow0 + mf * 16;
                a[mf][0] = f2tf32(As[(rb + gid) * AS_LD + kb + tig]);
                a[mf][1] = f2tf32(As[(rb + gid + 8) * AS_LD + kb + tig]);
                a[mf][2] = f2tf32(As[(rb + gid) * AS_LD + kb + tig + 4]);
                a[mf][3] = f2tf32(As[(rb + gid + 8) * AS_LD + kb + tig + 4]);
            }
            #pragma unroll
            for (int nt = 0; nt < 8; nt++) {
                int col = ncol0 + nt * 8 + gid;
                uint32_t b0 = f2tf32(Bs[(kb + tig) * BS_LD + col]);
                uint32_t b1 = f2tf32(Bs[(kb + tig + 4) * BS_LD + col]);
                mma_tf32(c[0][nt], a[0][0], a[0][1], a[0][2], a[0][3], b0, b1);
                mma_tf32(c[1][nt], a[1][0], a[1][1], a[1][2], a[1][3], b0, b1);
            }
        }
    }
    __syncthreads();
    #pragma unroll
    for (int mf = 0; mf < 2; mf++) {
        int rb = mrow0 + mf * 16;
        #pragma unroll
        for (int nt = 0; nt < 8; nt++) {
            int col0 = ncol0 + nt * 8 + 2 * tig;
            float bb0 = fc1b[col0], bb1 = fc1b[col0 + 1];
            Hs[(rb + gid) * HS_LD + col0]     = fmaxf(c[mf][nt][0] + bb0, 0.f);
            Hs[(rb + gid) * HS_LD + col0 + 1] = fmaxf(c[mf][nt][1] + bb1, 0.f);
            Hs[(rb + gid + 8) * HS_LD + col0]     = fmaxf(c[mf][nt][2] + bb0, 0.f);
            Hs[(rb + gid + 8) * HS_LD + col0 + 1] = fmaxf(c[mf][nt][3] + bb1, 0.f);
        }
    }
    __syncthreads();
    #pragma unroll
    for (int pp = 0; pp < 2; pp++) {
        int p = tid + pp * 512;
        int r = p >> 3, o = p & 7;
        size_t row = n0 + r;
        float a = fc2b[o];
        const float4* h4 = (const float4*)(Hs + r * HS_LD);
        const float4* w4 = (const float4*)(s_fc2 + o * 256);
        #pragma unroll 8
        for (int jj = 0; jj < 64; jj++) {
            float4 h = h4[jj], w = w4[jj];
            a += h.x * w.x + h.y * w.y + h.z * w.z + h.w * w.w;
        }
        if (row < NCELL) nodes_out[row * OUTD + o] = fmaxf(a, 0.f);
    }
    if (tid < 128) {
        size_t row = n0 + tid;
        if (row < NCELL) {
            float s = outb[0] + rpart4[tid][0] + rpart4[tid][1] + rpart4[tid][2] + rpart4[tid][3];
            ret_out[row] = s;
        }
    }
}

// ---------------- launch ----------------
static inline int cdiv(long long a, long long b) { return (int)((a + b - 1) / b); }

extern "C" void kernel_launch(void* const* d_in, const int* in_sizes, int n_in,
                              void* d_out, int out_size) {
    const float* node_f     = (const float*)d_in[0];
    const float* net_f      = (const float*)d_in[1];
    const int*   sink_node  = (const int*)d_in[2];
    const int*   sink_net   = (const int*)d_in[3];
    const int*   src_node   = (const int*)d_in[4];
    const int*   src_net    = (const int*)d_in[5];
    const int*   batch      = (const int*)d_in[6];
    const float* w_node     = (const float*)d_in[8];
    const float* b_node     = (const float*)d_in[9];
    const float* w_net      = (const float*)d_in[10];
    const float* b_net      = (const float*)d_in[11];
    const float* vn_emb     = (const float*)d_in[12];
    const float* vn_mlp_w   = (const float*)d_in[13];
    const float* vn_mlp_b   = (const float*)d_in[14];
    const float* conv_net_w = (const float*)d_in[15];
    const float* conv_net_b = (const float*)d_in[16];
    const float* conv_node_w= (const float*)d_in[17];
    const float* conv_node_b= (const float*)d_in[18];
    const float* fc1_w      = (const float*)d_in[19];
    const float* fc1_b      = (const float*)d_in[20];
    const float* fc2_w      = (const float*)d_in[21];
    const float* fc2_b      = (const float*)d_in[22];
    const float* out_w      = (const float*)d_in[23];
    const float* out_b      = (const float*)d_in[24];

    static bool attr_done = false;
    if (!attr_done) {
        cudaFuncSetAttribute(k_head_mma, cudaFuncAttributeMaxDynamicSharedMemorySize, DSMEM_HEAD);
        cudaFuncSetAttribute(k_net_mma, cudaFuncAttributeMaxDynamicSharedMemorySize, DSMEM_NET);
        cudaFuncSetAttribute(k_node_mma, cudaFuncAttributeMaxDynamicSharedMemorySize, DSMEM_NODE);
        attr_done = true;
    }

    float *p_cat, *p_net;
    cudaGetSymbolAddress((void**)&p_cat, g_cat);
    cudaGetSymbolAddress((void**)&p_net, g_net);

    // setup (9 launches)
    k_zero_all<<<cdiv(NCELL, 256), 256>>>();
    k_count<<<cdiv(EKE, 256), 256>>>(sink_node, sink_net, src_net);
    k_prep<<<cdiv(NCELL, 256), 256>>>(batch, vn_emb);
    k_embed<<<cdiv(NCELL, 32), 256>>>(node_f, w_node, b_node, p_cat, NCELL, CATD, 1, batch);
    k_embed<<<cdiv(MNET, 32), 256>>>(net_f, w_net, b_net, p_net, MNET, EMB, 0, nullptr);
    {
        int nb = cdiv(SCAN_TOT, 1024);
        k_scan1<<<nb, 256>>>();
        k_scan2<<<1, 1024>>>(nb);
        k_scan3<<<nb, 256>>>();
    }
    k_scat<<<cdiv(EKE, 256), 256>>>(sink_node, sink_net, src_node, src_net, batch);

    // layers (pool(0) fused into node embed)
    for (int l = 0; l < NL; l++) {
        k_net_mma<<<CONV_GRID, 256, DSMEM_NET>>>(conv_net_w + l * 4096, conv_net_b + l * 64, l);
        k_node_mma<<<CONV_GRID, 256, DSMEM_NODE>>>(conv_node_w + l * 4096, conv_node_b + l * 64, batch, l);
        if (l < NL - 1) {
            k_vn<<<VN, EMB>>>(vn_mlp_w + l * 4096, vn_mlp_b + l * 64);
            if (l + 1 < NL - 1)
                k_pool_cat<<<512, 256>>>(batch, l + 1);
        }
    }

    // head
    float* nodes_out = (float*)d_out;
    float* ret_out = (float*)d_out + (size_t)NCELL * OUTD;
    k_head_mma<<<cdiv(NCELL, 128), 512, DSMEM_HEAD>>>(fc1_w, fc1_b, fc2_w, fc2_b,
                                                      out_w, out_b, p_cat, nodes_out, ret_out);
}